// round 1
// baseline (speedup 1.0000x reference)
#include <cuda_runtime.h>
#include <cuda_bf16.h>

// Problem constants
#define BATCH 4
#define CIN   256
#define COUT  256
#define HH    64
#define WW    64
#define HW    4096          // 64*64
#define KTAPS 9
#define KCDIM 2304          // CIN * KTAPS
#define OFFCH 18            // 2*KTAPS
#define GNG   32
#define EPSGN 1e-5f

// ------------------------- device scratch (static, allocation-free) ----------
__device__ float g_offsets[BATCH * OFFCH * HW];                 // 1.18 MB
__device__ float g_wTT[(size_t)KCDIM * COUT];                   // 2.36 MB  [kc][oc]
__device__ float g_samp[(size_t)BATCH * KCDIM * HW];            // 151 MB   [b][kc][p]
__device__ float g_stats[BATCH * GNG * 2];                      // mean, rstd

// ------------------------- kernel 1: init offsets with bias ------------------
__global__ void init_offsets_kernel(const float* __restrict__ ob) {
    int i = blockIdx.x * 256 + threadIdx.x;
    if (i < BATCH * OFFCH * HW) {
        int ch = (i >> 12) % OFFCH;
        g_offsets[i] = ob[ch];
    }
}

// ------------------------- kernel 2: offset conv (3x3, 256->18) --------------
// 8 cin-groups of 32; weights for group cached in smem; atomicAdd partials.
__global__ void offset_conv_kernel(const float* __restrict__ x,
                                   const float* __restrict__ ow) {
    __shared__ float ws[OFFCH * 32 * 9];   // 5184 floats = 20.7 KB
    int g    = blockIdx.x >> 6;            // cin group 0..7
    int tile = blockIdx.x & 63;            // 64 pixel tiles of 256
    int tid  = threadIdx.x;

    for (int i = tid; i < OFFCH * 32 * 9; i += 256) {
        int j  = i % 9;
        int t  = i / 9;
        int ci = t % 32;
        int ch = t / 32;
        ws[i] = ow[(ch * CIN + g * 32 + ci) * 9 + j];
    }
    __syncthreads();

    int P  = tile * 256 + tid;             // global pixel 0..16383
    int b  = P >> 12;
    int p  = P & 4095;
    int y  = p >> 6;
    int xx = p & 63;

    int   off[9];
    float vmask[9];
#pragma unroll
    for (int ky = 0; ky < 3; ky++)
#pragma unroll
        for (int kx = 0; kx < 3; kx++) {
            int j  = ky * 3 + kx;
            int yy = y + ky - 1, xc = xx + kx - 1;
            vmask[j] = (yy >= 0 && yy < HH && xc >= 0 && xc < WW) ? 1.0f : 0.0f;
            off[j] = (ky - 1) * WW + (kx - 1);
        }

    float acc[OFFCH];
#pragma unroll
    for (int ch = 0; ch < OFFCH; ch++) acc[ch] = 0.0f;

    const float* xb = x + ((size_t)(b * CIN + g * 32)) * HW + p;
    for (int ci = 0; ci < 32; ci++) {
        const float* xc = xb + (size_t)ci * HW;
        float v[9];
#pragma unroll
        for (int j = 0; j < 9; j++)
            v[j] = (vmask[j] != 0.0f) ? xc[off[j]] : 0.0f;
#pragma unroll
        for (int ch = 0; ch < OFFCH; ch++) {
            const float* wc = &ws[(ch * 32 + ci) * 9];
            float a = acc[ch];
#pragma unroll
            for (int j = 0; j < 9; j++) a = fmaf(wc[j], v[j], a);
            acc[ch] = a;
        }
    }
#pragma unroll
    for (int ch = 0; ch < OFFCH; ch++)
        atomicAdd(&g_offsets[(b * OFFCH + ch) * HW + p], acc[ch]);
}

// ------------------------- kernel 3: repack deform weight --------------------
// deform_w[oc][c][k] (oc-major) -> wTT[k*256+c][oc]  (K-major, GEMM-friendly)
__global__ void repack_w_kernel(const float* __restrict__ dw) {
    int idx = blockIdx.x * 256 + threadIdx.x;      // 0 .. 589823
    if (idx < KCDIM * COUT) {
        int oc = idx & 255;
        int t  = idx >> 8;
        int c  = t & 255;
        int k  = t >> 8;
        g_wTT[idx] = dw[(size_t)oc * KCDIM + c * 9 + k];
    }
}

// ------------------------- kernel 4: bilinear sampling -----------------------
// lane = pixel (coalesced x reads + coalesced samp writes); warp strides over c.
__global__ void sample_kernel(const float* __restrict__ x) {
    int bk   = blockIdx.x >> 7;                 // (b,k) 0..35
    int tile = blockIdx.x & 127;                // 128 tiles of 32 pixels
    int b = bk / KTAPS, k = bk % KTAPS;
    int lane = threadIdx.x & 31;
    int warp = threadIdx.x >> 5;

    int p  = tile * 32 + lane;
    int y  = p >> 6;
    int xx = p & 63;

    float dy = g_offsets[(b * OFFCH + 2 * k)     * HW + p];
    float dx = g_offsets[(b * OFFCH + 2 * k + 1) * HW + p];
    int ky = k / 3, kx = k % 3;

    float py = (float)(y - 1 + ky) + dy;
    float px = (float)(xx - 1 + kx) + dx;
    float fy = floorf(py), fx = floorf(px);
    float ty = py - fy,   tx = px - fx;
    int y0 = (int)fy, x0 = (int)fx;
    int y1 = y0 + 1,  x1 = x0 + 1;

    float w00 = (1.f - ty) * (1.f - tx);
    float w01 = (1.f - ty) * tx;
    float w10 = ty * (1.f - tx);
    float w11 = ty * tx;

    bool vy0 = (y0 >= 0 && y0 < HH), vy1 = (y1 >= 0 && y1 < HH);
    bool vx0 = (x0 >= 0 && x0 < WW), vx1 = (x1 >= 0 && x1 < WW);
    if (!(vy0 && vx0)) w00 = 0.f;
    if (!(vy0 && vx1)) w01 = 0.f;
    if (!(vy1 && vx0)) w10 = 0.f;
    if (!(vy1 && vx1)) w11 = 0.f;

    int yc0 = min(max(y0, 0), HH - 1), yc1 = min(max(y1, 0), HH - 1);
    int xc0 = min(max(x0, 0), WW - 1), xc1 = min(max(x1, 0), WW - 1);
    int i00 = yc0 * WW + xc0, i01 = yc0 * WW + xc1;
    int i10 = yc1 * WW + xc0, i11 = yc1 * WW + xc1;

    const float* xb = x + (size_t)b * CIN * HW;
    float* sp = g_samp + ((size_t)(b * KCDIM + k * 256)) * HW + p;

    for (int c = warp; c < CIN; c += 8) {
        const float* xc = xb + (size_t)c * HW;
        float v = w00 * xc[i00] + w01 * xc[i01] + w10 * xc[i10] + w11 * xc[i11];
        sp[(size_t)c * HW] = v;
    }
}

// ------------------------- kernel 5: GEMM out[oc][p] = wTT^T * samp ---------
// M=256 (oc), N=16384 (pixels), K=2304. Tile 128x64, TK=16, double-buffered.
#define TM 128
#define TN 64
#define TK 16
#define NT (KCDIM / TK)   // 144

__global__ void __launch_bounds__(256, 2) gemm_kernel(float* __restrict__ out) {
    __shared__ float As[2][TK][TM];
    __shared__ float Bs[2][TK][TN];

    int nt = blockIdx.x;                  // 0..255
    int mt = blockIdx.y;                  // 0..1
    int tid = threadIdx.x;

    int P0 = nt * TN;
    int b  = P0 >> 12;
    int p0 = P0 & 4095;
    int m0 = mt * TM;

    const float* Aptr = g_wTT;                              // [KC][256]
    const float* Bptr = g_samp + (size_t)b * KCDIM * HW;    // [KC][4096]

    float acc[8][4];
#pragma unroll
    for (int i = 0; i < 8; i++)
#pragma unroll
        for (int j = 0; j < 4; j++) acc[i][j] = 0.0f;

    // prologue: chunk 0 -> smem buffer 0
#pragma unroll
    for (int i = 0; i < 8; i++) {
        int id = i * 256 + tid, ka = id >> 7, ma = id & 127;
        As[0][ka][ma] = Aptr[(size_t)ka * COUT + m0 + ma];
    }
#pragma unroll
    for (int i = 0; i < 4; i++) {
        int id = i * 256 + tid, kb = id >> 6, nb = id & 63;
        Bs[0][kb][nb] = Bptr[(size_t)kb * HW + p0 + nb];
    }
    __syncthreads();

    int tx = tid & 15;   // n quad
    int ty = tid >> 4;   // m oct

    float ra[8], rb[4];
    for (int t = 0; t < NT; t++) {
        int cur = t & 1;
        if (t < NT - 1) {
            int kc0 = (t + 1) * TK;
#pragma unroll
            for (int i = 0; i < 8; i++) {
                int id = i * 256 + tid, ka = id >> 7, ma = id & 127;
                ra[i] = Aptr[(size_t)(kc0 + ka) * COUT + m0 + ma];
            }
#pragma unroll
            for (int i = 0; i < 4; i++) {
                int id = i * 256 + tid, kb = id >> 6, nb = id & 63;
                rb[i] = Bptr[(size_t)(kc0 + kb) * HW + p0 + nb];
            }
        }
#pragma unroll
        for (int kk = 0; kk < TK; kk++) {
            float4 a0 = *(const float4*)&As[cur][kk][ty * 8];
            float4 a1 = *(const float4*)&As[cur][kk][ty * 8 + 4];
            float4 bb = *(const float4*)&Bs[cur][kk][tx * 4];
            float a[8] = {a0.x, a0.y, a0.z, a0.w, a1.x, a1.y, a1.z, a1.w};
            float bv[4] = {bb.x, bb.y, bb.z, bb.w};
#pragma unroll
            for (int i = 0; i < 8; i++)
#pragma unroll
                for (int j = 0; j < 4; j++)
                    acc[i][j] = fmaf(a[i], bv[j], acc[i][j]);
        }
        if (t < NT - 1) {
            int nxt = cur ^ 1;
#pragma unroll
            for (int i = 0; i < 8; i++) {
                int id = i * 256 + tid, ka = id >> 7, ma = id & 127;
                As[nxt][ka][ma] = ra[i];
            }
#pragma unroll
            for (int i = 0; i < 4; i++) {
                int id = i * 256 + tid, kb = id >> 6, nb = id & 63;
                Bs[nxt][kb][nb] = rb[i];
            }
        }
        __syncthreads();
    }

    float* ob = out + (size_t)b * COUT * HW + p0;
#pragma unroll
    for (int i = 0; i < 8; i++) {
        int oc = m0 + ty * 8 + i;
        float4 v = make_float4(acc[i][0], acc[i][1], acc[i][2], acc[i][3]);
        *(float4*)(ob + (size_t)oc * HW + tx * 4) = v;
    }
}

// ------------------------- kernel 6: GroupNorm stats -------------------------
__global__ void gn_stats_kernel(const float* __restrict__ out) {
    __shared__ float sh_s[256], sh_ss[256];
    int bg = blockIdx.x;                                    // 0..127, (b,g)
    const float4* src = (const float4*)(out + (size_t)bg * 8 * HW);
    float s = 0.f, ss = 0.f;
    for (int i = threadIdx.x; i < 8 * HW / 4; i += 256) {
        float4 v = src[i];
        s  += v.x + v.y + v.z + v.w;
        ss += v.x * v.x + v.y * v.y + v.z * v.z + v.w * v.w;
    }
    sh_s[threadIdx.x] = s;
    sh_ss[threadIdx.x] = ss;
    __syncthreads();
    for (int stride = 128; stride > 0; stride >>= 1) {
        if (threadIdx.x < stride) {
            sh_s[threadIdx.x]  += sh_s[threadIdx.x + stride];
            sh_ss[threadIdx.x] += sh_ss[threadIdx.x + stride];
        }
        __syncthreads();
    }
    if (threadIdx.x == 0) {
        const float inv_n = 1.0f / (8.0f * HW);
        float mu  = sh_s[0] * inv_n;
        float var = sh_ss[0] * inv_n - mu * mu;
        g_stats[bg * 2]     = mu;
        g_stats[bg * 2 + 1] = rsqrtf(var + EPSGN);
    }
}

// ------------------------- kernel 7: GroupNorm apply + ReLU (in place) -------
__global__ void gn_apply_kernel(float* __restrict__ out,
                                const float* __restrict__ gamma,
                                const float* __restrict__ beta) {
    int i = blockIdx.x * 256 + threadIdx.x;                 // float4 index
    if (i >= BATCH * COUT * HW / 4) return;
    int base = i * 4;
    int bg = base / (8 * HW);
    int c  = (base >> 12) & 255;
    float mu   = g_stats[bg * 2];
    float rstd = g_stats[bg * 2 + 1];
    float gsc  = gamma[c] * rstd;
    float gbi  = beta[c] - mu * gsc;
    float4* p = (float4*)out + i;
    float4 v = *p;
    v.x = fmaxf(0.f, fmaf(v.x, gsc, gbi));
    v.y = fmaxf(0.f, fmaf(v.y, gsc, gbi));
    v.z = fmaxf(0.f, fmaf(v.z, gsc, gbi));
    v.w = fmaxf(0.f, fmaf(v.w, gsc, gbi));
    *p = v;
}

// ------------------------- launch ------------------------------------------
extern "C" void kernel_launch(void* const* d_in, const int* in_sizes, int n_in,
                              void* d_out, int out_size) {
    const float* x        = (const float*)d_in[0];
    const float* offset_w = (const float*)d_in[1];
    const float* offset_b = (const float*)d_in[2];
    const float* deform_w = (const float*)d_in[3];
    const float* gn_gamma = (const float*)d_in[4];
    const float* gn_beta  = (const float*)d_in[5];
    float* out = (float*)d_out;

    init_offsets_kernel<<<(BATCH * OFFCH * HW + 255) / 256, 256>>>(offset_b);
    offset_conv_kernel<<<512, 256>>>(x, offset_w);
    repack_w_kernel<<<(KCDIM * COUT + 255) / 256, 256>>>(deform_w);
    sample_kernel<<<BATCH * KTAPS * (HW / 32), 256>>>(x);
    {
        dim3 grid(HW * BATCH / TN, COUT / TM);
        gemm_kernel<<<grid, 256>>>(out);
    }
    gn_stats_kernel<<<BATCH * GNG, 256>>>(out);
    gn_apply_kernel<<<(BATCH * COUT * HW / 4 + 255) / 256, 256>>>(out, gn_gamma, gn_beta);
}

// round 4
// speedup vs baseline: 1.7337x; 1.7337x over previous
#include <cuda_runtime.h>
#include <cuda_bf16.h>
#include <cstdint>

// Problem constants
#define BATCH 4
#define CIN   256
#define COUT  256
#define HH    64
#define WW    64
#define HW    4096
#define KTAPS 9
#define KCDIM 2304          // CIN * KTAPS
#define OFFCH 18
#define GNG   32
#define EPSGN 1e-5f

// ------------------------- helpers ------------------------------------------
__device__ __forceinline__ float to_tf32(float x) {
    float y;
    asm("cvt.rna.tf32.f32 %0, %1;" : "=f"(y) : "f"(x));
    return y;
}
__device__ __forceinline__ uint32_t smem_u32(const void* p) {
    uint32_t a;
    asm("{ .reg .u64 t; cvta.to.shared.u64 t, %1; cvt.u32.u64 %0, t; }" : "=r"(a) : "l"(p));
    return a;
}
__device__ __forceinline__ void cp16(uint32_t s, const void* g) {
    asm volatile("cp.async.cg.shared.global [%0], [%1], 16;" :: "r"(s), "l"(g));
}
#define CP_COMMIT() asm volatile("cp.async.commit_group;" ::: "memory")
#define CP_WAIT0()  asm volatile("cp.async.wait_group 0;" ::: "memory")

__device__ __forceinline__ void mma_tf32_16x8x8(float* d, const uint32_t* a, const uint32_t* b) {
    asm volatile(
        "mma.sync.aligned.m16n8k8.row.col.f32.tf32.tf32.f32 "
        "{%0,%1,%2,%3}, {%4,%5,%6,%7}, {%8,%9}, {%0,%1,%2,%3};"
        : "+f"(d[0]), "+f"(d[1]), "+f"(d[2]), "+f"(d[3])
        : "r"(a[0]), "r"(a[1]), "r"(a[2]), "r"(a[3]), "r"(b[0]), "r"(b[1]));
}

// ------------------------- device scratch ------------------------------------
__device__ float g_offsets[BATCH * OFFCH * HW];                 // 1.18 MB
__device__ float g_wA[(size_t)COUT * KCDIM];                    // [oc][k*256+c], tf32-rounded
__device__ float g_samp[(size_t)BATCH * HW * KCDIM];            // [b*4096+p][kc], tf32-rounded
__device__ float g_stats[BATCH * GNG * 2];

// ------------------------- kernel 1: init offsets with bias ------------------
__global__ void init_offsets_kernel(const float* __restrict__ ob) {
    int i = blockIdx.x * 256 + threadIdx.x;
    if (i < BATCH * OFFCH * HW) {
        int ch = (i >> 12) % OFFCH;
        g_offsets[i] = ob[ch];
    }
}

// ------------------------- kernel 2: offset conv (3x3, 256->18) --------------
__global__ void offset_conv_kernel(const float* __restrict__ x,
                                   const float* __restrict__ ow) {
    __shared__ float ws[OFFCH * 32 * 9];
    int g    = blockIdx.x >> 6;
    int tile = blockIdx.x & 63;
    int tid  = threadIdx.x;

    for (int i = tid; i < OFFCH * 32 * 9; i += 256) {
        int j  = i % 9;
        int t  = i / 9;
        int ci = t % 32;
        int ch = t / 32;
        ws[i] = ow[(ch * CIN + g * 32 + ci) * 9 + j];
    }
    __syncthreads();

    int P  = tile * 256 + tid;
    int b  = P >> 12;
    int p  = P & 4095;
    int y  = p >> 6;
    int xx = p & 63;

    int   off[9];
    float vmask[9];
#pragma unroll
    for (int ky = 0; ky < 3; ky++)
#pragma unroll
        for (int kx = 0; kx < 3; kx++) {
            int j  = ky * 3 + kx;
            int yy = y + ky - 1, xc = xx + kx - 1;
            vmask[j] = (yy >= 0 && yy < HH && xc >= 0 && xc < WW) ? 1.0f : 0.0f;
            off[j] = (ky - 1) * WW + (kx - 1);
        }

    float acc[OFFCH];
#pragma unroll
    for (int ch = 0; ch < OFFCH; ch++) acc[ch] = 0.0f;

    const float* xb = x + ((size_t)(b * CIN + g * 32)) * HW + p;
    for (int ci = 0; ci < 32; ci++) {
        const float* xc = xb + (size_t)ci * HW;
        float v[9];
#pragma unroll
        for (int j = 0; j < 9; j++)
            v[j] = (vmask[j] != 0.0f) ? xc[off[j]] : 0.0f;
#pragma unroll
        for (int ch = 0; ch < OFFCH; ch++) {
            const float* wc = &ws[(ch * 32 + ci) * 9];
            float a = acc[ch];
#pragma unroll
            for (int j = 0; j < 9; j++) a = fmaf(wc[j], v[j], a);
            acc[ch] = a;
        }
    }
#pragma unroll
    for (int ch = 0; ch < OFFCH; ch++)
        atomicAdd(&g_offsets[(b * OFFCH + ch) * HW + p], acc[ch]);
}

// ------------------------- kernel 3: repack weights (tf32-rounded) -----------
// deform_w[oc][c][k] -> wA[oc][k*256+c]
__global__ void repack_w_kernel(const float* __restrict__ dw) {
    int idx = blockIdx.x * 256 + threadIdx.x;
    if (idx < COUT * KCDIM) {
        int r  = idx % KCDIM;
        int oc = idx / KCDIM;
        int k  = r >> 8;
        int c  = r & 255;
        g_wA[idx] = to_tf32(dw[(size_t)oc * KCDIM + c * 9 + k]);
    }
}

// ------------------------- kernel 4: bilinear sampling + transpose -----------
// block = 32 pixels; gathers with lane=pixel (coalesced), SMEM transpose,
// writes g_samp[pixel][kc] (tf32-rounded) with 128B contiguous per thread.
__global__ void __launch_bounds__(256) sample_kernel(const float* __restrict__ x) {
    __shared__ float vsm[256 * 32];
    int b     = blockIdx.x >> 7;
    int ptile = blockIdx.x & 127;
    int lane  = threadIdx.x & 31;
    int warp  = threadIdx.x >> 5;
    int p  = ptile * 32 + lane;
    int y  = p >> 6;
    int xx = p & 63;
    const float* xb = x + (size_t)b * CIN * HW;

    int wpix = threadIdx.x >> 3;   // 0..31 : pixel for writes
    int wcb  = threadIdx.x & 7;    // 0..7  : c-block for writes
    float* outRow = g_samp + (size_t)(b * HW + ptile * 32 + wpix) * KCDIM;
    int wrot = (wpix + 4 * wcb) & 31;

    for (int k = 0; k < KTAPS; k++) {
        float dy = g_offsets[(b * OFFCH + 2 * k)     * HW + p];
        float dx = g_offsets[(b * OFFCH + 2 * k + 1) * HW + p];
        int ky = k / 3, kx = k % 3;

        float py = (float)(y - 1 + ky) + dy;
        float px = (float)(xx - 1 + kx) + dx;
        float fy = floorf(py), fx = floorf(px);
        float ty = py - fy,   tx = px - fx;
        int y0 = (int)fy, x0 = (int)fx;
        int y1 = y0 + 1,  x1 = x0 + 1;

        float w00 = (1.f - ty) * (1.f - tx);
        float w01 = (1.f - ty) * tx;
        float w10 = ty * (1.f - tx);
        float w11 = ty * tx;

        bool vy0 = (y0 >= 0 && y0 < HH), vy1 = (y1 >= 0 && y1 < HH);
        bool vx0 = (x0 >= 0 && x0 < WW), vx1 = (x1 >= 0 && x1 < WW);
        if (!(vy0 && vx0)) w00 = 0.f;
        if (!(vy0 && vx1)) w01 = 0.f;
        if (!(vy1 && vx0)) w10 = 0.f;
        if (!(vy1 && vx1)) w11 = 0.f;

        int yc0 = min(max(y0, 0), HH - 1), yc1 = min(max(y1, 0), HH - 1);
        int xc0 = min(max(x0, 0), WW - 1), xc1 = min(max(x1, 0), WW - 1);
        int i00 = yc0 * WW + xc0, i01 = yc0 * WW + xc1;
        int i10 = yc1 * WW + xc0, i11 = yc1 * WW + xc1;

        for (int c = warp; c < CIN; c += 8) {
            const float* xc = xb + (size_t)c * HW;
            float v = w00 * xc[i00] + w01 * xc[i01] + w10 * xc[i10] + w11 * xc[i11];
            vsm[c * 32 + ((lane + 4 * (c >> 5)) & 31)] = v;
        }
        __syncthreads();

#pragma unroll
        for (int j = 0; j < 8; j++) {
            int c0 = wcb * 32 + j * 4;
            float4 v4;
            v4.x = to_tf32(vsm[(c0 + 0) * 32 + wrot]);
            v4.y = to_tf32(vsm[(c0 + 1) * 32 + wrot]);
            v4.z = to_tf32(vsm[(c0 + 2) * 32 + wrot]);
            v4.w = to_tf32(vsm[(c0 + 3) * 32 + wrot]);
            *(float4*)(outRow + k * 256 + c0) = v4;
        }
        __syncthreads();
    }
}

// ------------------------- kernel 5: mma.sync tf32 GEMM ----------------------
// C[oc=128 (by)][p=128 (bx)] per CTA. A = g_wA rows (K-major), B = g_samp rows
// (K-major). K-chunks of 32 floats, double-buffered via cp.async.
// 8 warps = 2(m) x 4(n); warp tile 64x32 -> 4x4 m16n8k8 tiles.
#define ASTR 36                     // padded row stride (floats)
#define TILE_F (128 * ASTR)         // floats per (stage, matrix)
#define GEMM_SMEM (4 * TILE_F * 4)  // 2 stages * (A+B) * 4 B = 73728 B
#define KT 72

__global__ void __launch_bounds__(256, 2) gemm_mma_kernel(float* __restrict__ out) {
    extern __shared__ float sm[];
    float* As = sm;                 // [2][128][ASTR]
    float* Bs = sm + 2 * TILE_F;    // [2][128][ASTR]
    uint32_t As_u = smem_u32(As);
    uint32_t Bs_u = smem_u32(Bs);

    const int tid  = threadIdx.x;
    const int lane = tid & 31;
    const int wid  = tid >> 5;
    const int wm   = wid >> 2;      // 0..1  (m offset wm*64)
    const int wn   = wid & 3;       // 0..3  (n offset wn*32)

    const int P0 = blockIdx.x * 128;
    const int b  = P0 >> 12;
    const int p0 = P0 & 4095;
    const int m0 = blockIdx.y * 128;

    const float* Ag = g_wA + (size_t)m0 * KCDIM;
    const float* Bg = g_samp + (size_t)(b * HW + p0) * KCDIM;

    const int lrow = tid >> 3;      // 0..31 loader row base (+32*it)
    const int lc4  = tid & 7;       // 0..7  loader float4 within 32-float chunk

    float acc[16][4];
#pragma unroll
    for (int i = 0; i < 16; i++)
#pragma unroll
        for (int j = 0; j < 4; j++) acc[i][j] = 0.0f;

    // prologue: chunk 0 -> stage 0
#pragma unroll
    for (int it = 0; it < 4; it++) {
        int row = lrow + it * 32;
        cp16(As_u + (row * ASTR + lc4 * 4) * 4, Ag + (size_t)row * KCDIM + lc4 * 4);
        cp16(Bs_u + (row * ASTR + lc4 * 4) * 4, Bg + (size_t)row * KCDIM + lc4 * 4);
    }
    CP_COMMIT();
    CP_WAIT0();
    __syncthreads();

    const int fr = lane >> 2;       // 0..7
    const int fc = lane & 3;        // 0..3

    for (int t = 0; t < KT; t++) {
        int cur = t & 1;
        if (t + 1 < KT) {
            int nxt = cur ^ 1;
            const float* Asrc = Ag + (t + 1) * 32;
            const float* Bsrc = Bg + (t + 1) * 32;
            uint32_t aD = As_u + nxt * TILE_F * 4;
            uint32_t bD = Bs_u + nxt * TILE_F * 4;
#pragma unroll
            for (int it = 0; it < 4; it++) {
                int row = lrow + it * 32;
                cp16(aD + (row * ASTR + lc4 * 4) * 4, Asrc + (size_t)row * KCDIM + lc4 * 4);
                cp16(bD + (row * ASTR + lc4 * 4) * 4, Bsrc + (size_t)row * KCDIM + lc4 * 4);
            }
            CP_COMMIT();
        }

        const float* Ab = As + cur * TILE_F + (wm * 64) * ASTR;
        const float* Bb = Bs + cur * TILE_F + (wn * 32) * ASTR;

#pragma unroll
        for (int ks = 0; ks < 4; ks++) {
            int k0 = ks * 8;
            uint32_t af[4][4];
#pragma unroll
            for (int mt = 0; mt < 4; mt++) {
                int r0 = mt * 16 + fr;
                af[mt][0] = __float_as_uint(Ab[r0 * ASTR + k0 + fc]);
                af[mt][1] = __float_as_uint(Ab[(r0 + 8) * ASTR + k0 + fc]);
                af[mt][2] = __float_as_uint(Ab[r0 * ASTR + k0 + fc + 4]);
                af[mt][3] = __float_as_uint(Ab[(r0 + 8) * ASTR + k0 + fc + 4]);
            }
            uint32_t bf[4][2];
#pragma unroll
            for (int nt = 0; nt < 4; nt++) {
                int c0 = nt * 8 + fr;
                bf[nt][0] = __float_as_uint(Bb[c0 * ASTR + k0 + fc]);
                bf[nt][1] = __float_as_uint(Bb[c0 * ASTR + k0 + fc + 4]);
            }
#pragma unroll
            for (int mt = 0; mt < 4; mt++)
#pragma unroll
                for (int nt = 0; nt < 4; nt++)
                    mma_tf32_16x8x8(acc[mt * 4 + nt], af[mt], bf[nt]);
        }

        if (t + 1 < KT) CP_WAIT0();
        __syncthreads();
    }

    // epilogue
    float* ob = out + ((size_t)b * COUT + m0 + wm * 64) * HW + p0 + wn * 32;
#pragma unroll
    for (int mt = 0; mt < 4; mt++) {
#pragma unroll
        for (int nt = 0; nt < 4; nt++) {
            float* d = acc[mt * 4 + nt];
            int row0 = mt * 16 + (lane >> 2);
            int col0 = nt * 8 + 2 * (lane & 3);
            *(float2*)(ob + (size_t)row0 * HW + col0)       = make_float2(d[0], d[1]);
            *(float2*)(ob + (size_t)(row0 + 8) * HW + col0) = make_float2(d[2], d[3]);
        }
    }
}

// ------------------------- kernel 6: GroupNorm stats -------------------------
__global__ void gn_stats_kernel(const float* __restrict__ out) {
    __shared__ float sh_s[256], sh_ss[256];
    int bg = blockIdx.x;
    const float4* src = (const float4*)(out + (size_t)bg * 8 * HW);
    float s = 0.f, ss = 0.f;
    for (int i = threadIdx.x; i < 8 * HW / 4; i += 256) {
        float4 v = src[i];
        s  += v.x + v.y + v.z + v.w;
        ss += v.x * v.x + v.y * v.y + v.z * v.z + v.w * v.w;
    }
    sh_s[threadIdx.x] = s;
    sh_ss[threadIdx.x] = ss;
    __syncthreads();
    for (int stride = 128; stride > 0; stride >>= 1) {
        if (threadIdx.x < stride) {
            sh_s[threadIdx.x]  += sh_s[threadIdx.x + stride];
            sh_ss[threadIdx.x] += sh_ss[threadIdx.x + stride];
        }
        __syncthreads();
    }
    if (threadIdx.x == 0) {
        const float inv_n = 1.0f / (8.0f * HW);
        float mu  = sh_s[0] * inv_n;
        float var = sh_ss[0] * inv_n - mu * mu;
        g_stats[bg * 2]     = mu;
        g_stats[bg * 2 + 1] = rsqrtf(var + EPSGN);
    }
}

// ------------------------- kernel 7: GroupNorm apply + ReLU ------------------
__global__ void gn_apply_kernel(float* __restrict__ out,
                                const float* __restrict__ gamma,
                                const float* __restrict__ beta) {
    int i = blockIdx.x * 256 + threadIdx.x;
    if (i >= BATCH * COUT * HW / 4) return;
    int base = i * 4;
    int bg = base / (8 * HW);
    int c  = (base >> 12) & 255;
    float mu   = g_stats[bg * 2];
    float rstd = g_stats[bg * 2 + 1];
    float gsc  = gamma[c] * rstd;
    float gbi  = beta[c] - mu * gsc;
    float4* p = (float4*)out + i;
    float4 v = *p;
    v.x = fmaxf(0.f, fmaf(v.x, gsc, gbi));
    v.y = fmaxf(0.f, fmaf(v.y, gsc, gbi));
    v.z = fmaxf(0.f, fmaf(v.z, gsc, gbi));
    v.w = fmaxf(0.f, fmaf(v.w, gsc, gbi));
    *p = v;
}

// ------------------------- launch -------------------------------------------
extern "C" void kernel_launch(void* const* d_in, const int* in_sizes, int n_in,
                              void* d_out, int out_size) {
    const float* x        = (const float*)d_in[0];
    const float* offset_w = (const float*)d_in[1];
    const float* offset_b = (const float*)d_in[2];
    const float* deform_w = (const float*)d_in[3];
    const float* gn_gamma = (const float*)d_in[4];
    const float* gn_beta  = (const float*)d_in[5];
    float* out = (float*)d_out;

    static bool configured = false;
    if (!configured) {
        cudaFuncSetAttribute(gemm_mma_kernel,
                             cudaFuncAttributeMaxDynamicSharedMemorySize, GEMM_SMEM);
        configured = true;
    }

    init_offsets_kernel<<<(BATCH * OFFCH * HW + 255) / 256, 256>>>(offset_b);
    offset_conv_kernel<<<512, 256>>>(x, offset_w);
    repack_w_kernel<<<((int)(COUT * KCDIM) + 255) / 256, 256>>>(deform_w);
    sample_kernel<<<BATCH * (HW / 32), 256>>>(x);
    {
        dim3 grid(BATCH * HW / 128, COUT / 128);
        gemm_mma_kernel<<<grid, 256, GEMM_SMEM>>>(out);
    }
    gn_stats_kernel<<<BATCH * GNG, 256>>>(out);
    gn_apply_kernel<<<(BATCH * COUT * HW / 4 + 255) / 256, 256>>>(out, gn_gamma, gn_beta);
}

// round 7
// speedup vs baseline: 1.7624x; 1.0166x over previous
#include <cuda_runtime.h>
#include <cuda_bf16.h>
#include <cstdint>

// Problem constants
#define BATCH 4
#define CIN   256
#define COUT  256
#define HH    64
#define WW    64
#define HW    4096
#define KTAPS 9
#define KCDIM 2304          // CIN * KTAPS
#define OFFCH 18
#define GNG   32
#define EPSGN 1e-5f

// ------------------------- helpers ------------------------------------------
__device__ __forceinline__ float to_tf32(float x) {
    float y;
    asm("cvt.rna.tf32.f32 %0, %1;" : "=f"(y) : "f"(x));
    return y;
}
__device__ __forceinline__ uint32_t smem_u32(const void* p) {
    uint32_t a;
    asm("{ .reg .u64 t; cvta.to.shared.u64 t, %1; cvt.u32.u64 %0, t; }" : "=r"(a) : "l"(p));
    return a;
}
__device__ __forceinline__ void cp16(uint32_t s, const void* g) {
    asm volatile("cp.async.cg.shared.global [%0], [%1], 16;" :: "r"(s), "l"(g));
}
#define CP_COMMIT() asm volatile("cp.async.commit_group;" ::: "memory")
#define CP_WAIT0()  asm volatile("cp.async.wait_group 0;" ::: "memory")

__device__ __forceinline__ void mma_tf32_16x8x8(float* d, const uint32_t* a, const uint32_t* b) {
    asm volatile(
        "mma.sync.aligned.m16n8k8.row.col.f32.tf32.tf32.f32 "
        "{%0,%1,%2,%3}, {%4,%5,%6,%7}, {%8,%9}, {%0,%1,%2,%3};"
        : "+f"(d[0]), "+f"(d[1]), "+f"(d[2]), "+f"(d[3])
        : "r"(a[0]), "r"(a[1]), "r"(a[2]), "r"(a[3]), "r"(b[0]), "r"(b[1]));
}

// ------------------------- device scratch ------------------------------------
__device__ float g_offsets[BATCH * OFFCH * HW];                 // 1.18 MB
__device__ float g_wA[(size_t)COUT * KCDIM];                    // [oc][k*256+c], tf32-rounded
__device__ float g_samp[(size_t)BATCH * HW * KCDIM];            // [b*4096+p][kc], tf32-rounded
__device__ float g_stats[BATCH * GNG * 2];

// ------------------------- kernel 1: init offsets with bias ------------------
__global__ void init_offsets_kernel(const float* __restrict__ ob) {
    int i = blockIdx.x * 256 + threadIdx.x;
    if (i < BATCH * OFFCH * HW) {
        int ch = (i >> 12) % OFFCH;
        g_offsets[i] = ob[ch];
    }
}

// ------------------------- kernel 2: offset conv (3x3, 256->18) --------------
__global__ void offset_conv_kernel(const float* __restrict__ x,
                                   const float* __restrict__ ow) {
    __shared__ float ws[OFFCH * 32 * 9];
    int g    = blockIdx.x >> 6;
    int tile = blockIdx.x & 63;
    int tid  = threadIdx.x;

    for (int i = tid; i < OFFCH * 32 * 9; i += 256) {
        int j  = i % 9;
        int t  = i / 9;
        int ci = t % 32;
        int ch = t / 32;
        ws[i] = ow[(ch * CIN + g * 32 + ci) * 9 + j];
    }
    __syncthreads();

    int P  = tile * 256 + tid;
    int b  = P >> 12;
    int p  = P & 4095;
    int y  = p >> 6;
    int xx = p & 63;

    int   off[9];
    float vmask[9];
#pragma unroll
    for (int ky = 0; ky < 3; ky++)
#pragma unroll
        for (int kx = 0; kx < 3; kx++) {
            int j  = ky * 3 + kx;
            int yy = y + ky - 1, xc = xx + kx - 1;
            vmask[j] = (yy >= 0 && yy < HH && xc >= 0 && xc < WW) ? 1.0f : 0.0f;
            off[j] = (ky - 1) * WW + (kx - 1);
        }

    float acc[OFFCH];
#pragma unroll
    for (int ch = 0; ch < OFFCH; ch++) acc[ch] = 0.0f;

    const float* xb = x + ((size_t)(b * CIN + g * 32)) * HW + p;
    for (int ci = 0; ci < 32; ci++) {
        const float* xc = xb + (size_t)ci * HW;
        float v[9];
#pragma unroll
        for (int j = 0; j < 9; j++)
            v[j] = (vmask[j] != 0.0f) ? xc[off[j]] : 0.0f;
#pragma unroll
        for (int ch = 0; ch < OFFCH; ch++) {
            const float* wc = &ws[(ch * 32 + ci) * 9];
            float a = acc[ch];
#pragma unroll
            for (int j = 0; j < 9; j++) a = fmaf(wc[j], v[j], a);
            acc[ch] = a;
        }
    }
#pragma unroll
    for (int ch = 0; ch < OFFCH; ch++)
        atomicAdd(&g_offsets[(b * OFFCH + ch) * HW + p], acc[ch]);
}

// ------------------------- kernel 3: repack weights (tf32-rounded) -----------
// deform_w[oc][c][k] -> wA[oc][k*256+c]
__global__ void repack_w_kernel(const float* __restrict__ dw) {
    int idx = blockIdx.x * 256 + threadIdx.x;
    if (idx < COUT * KCDIM) {
        int r  = idx % KCDIM;
        int oc = idx / KCDIM;
        int k  = r >> 8;
        int c  = r & 255;
        g_wA[idx] = to_tf32(dw[(size_t)oc * KCDIM + c * 9 + k]);
    }
}

// ------------------------- kernel 4: bilinear sampling + transpose -----------
// One CTA per (batch, tap, 32-pixel tile): grid = 4*9*128 = 4608.
// Gather with lane=pixel (coalesced); transpose via 8KB SMEM (1 sync);
// write g_samp[pixel][k*256 + c] as contiguous 128B float4 per thread.
__global__ void __launch_bounds__(256) sample_kernel(const float* __restrict__ x) {
    __shared__ float vsm[256 * 32];           // 8 KB : [c][rot(pixel)]
    int id    = blockIdx.x;
    int ptile = id & 127;  id >>= 7;          // 0..127
    int k     = id % KTAPS;
    int b     = id / KTAPS;

    int lane  = threadIdx.x & 31;
    int warp  = threadIdx.x >> 5;
    int p  = ptile * 32 + lane;
    int y  = p >> 6;
    int xx = p & 63;
    const float* xb = x + (size_t)b * CIN * HW;

    float dy = g_offsets[(b * OFFCH + 2 * k)     * HW + p];
    float dx = g_offsets[(b * OFFCH + 2 * k + 1) * HW + p];
    int ky = k / 3, kx = k % 3;

    float py = (float)(y - 1 + ky) + dy;
    float px = (float)(xx - 1 + kx) + dx;
    float fy = floorf(py), fx = floorf(px);
    float ty = py - fy,   tx = px - fx;
    int y0 = (int)fy, x0 = (int)fx;
    int y1 = y0 + 1,  x1 = x0 + 1;

    float w00 = (1.f - ty) * (1.f - tx);
    float w01 = (1.f - ty) * tx;
    float w10 = ty * (1.f - tx);
    float w11 = ty * tx;

    bool vy0 = (y0 >= 0 && y0 < HH), vy1 = (y1 >= 0 && y1 < HH);
    bool vx0 = (x0 >= 0 && x0 < WW), vx1 = (x1 >= 0 && x1 < WW);
    if (!(vy0 && vx0)) w00 = 0.f;
    if (!(vy0 && vx1)) w01 = 0.f;
    if (!(vy1 && vx0)) w10 = 0.f;
    if (!(vy1 && vx1)) w11 = 0.f;

    int yc0 = min(max(y0, 0), HH - 1), yc1 = min(max(y1, 0), HH - 1);
    int xc0 = min(max(x0, 0), WW - 1), xc1 = min(max(x1, 0), WW - 1);
    int i00 = yc0 * WW + xc0, i01 = yc0 * WW + xc1;
    int i10 = yc1 * WW + xc0, i11 = yc1 * WW + xc1;

    for (int c = warp; c < CIN; c += 8) {
        const float* xc = xb + (size_t)c * HW;
        float v = w00 * xc[i00] + w01 * xc[i01] + w10 * xc[i10] + w11 * xc[i11];
        vsm[c * 32 + ((lane + 4 * (c >> 5)) & 31)] = v;
    }
    __syncthreads();

    int wpix = threadIdx.x >> 3;   // 0..31 : pixel for writes
    int wcb  = threadIdx.x & 7;    // 0..7  : 32-channel block for writes
    int wrot = (wpix + 4 * wcb) & 31;
    float* outRow = g_samp + (size_t)(b * HW + ptile * 32 + wpix) * KCDIM + k * 256;

#pragma unroll
    for (int j = 0; j < 8; j++) {
        int c0 = wcb * 32 + j * 4;
        float4 v4;
        v4.x = to_tf32(vsm[(c0 + 0) * 32 + wrot]);
        v4.y = to_tf32(vsm[(c0 + 1) * 32 + wrot]);
        v4.z = to_tf32(vsm[(c0 + 2) * 32 + wrot]);
        v4.w = to_tf32(vsm[(c0 + 3) * 32 + wrot]);
        *(float4*)(outRow + c0) = v4;
    }
}

// ------------------------- kernel 5: mma.sync tf32 GEMM ----------------------
// C[oc=128 (by)][p=128 (bx)] per CTA. A = g_wA rows (K-major), B = g_samp rows
// (K-major). K-chunks of 32 floats, double-buffered via cp.async.
// 8 warps = 2(m) x 4(n); warp tile 64x32 -> 4x4 m16n8k8 tiles.
#define ASTR 36                     // padded row stride (floats)
#define TILE_F (128 * ASTR)         // floats per (stage, matrix)
#define GEMM_SMEM (4 * TILE_F * 4)  // 2 stages * (A+B) * 4 B = 73728 B
#define KT 72

__global__ void __launch_bounds__(256, 2) gemm_mma_kernel(float* __restrict__ out) {
    extern __shared__ float sm[];
    float* As = sm;                 // [2][128][ASTR]
    float* Bs = sm + 2 * TILE_F;    // [2][128][ASTR]
    uint32_t As_u = smem_u32(As);
    uint32_t Bs_u = smem_u32(Bs);

    const int tid  = threadIdx.x;
    const int lane = tid & 31;
    const int wid  = tid >> 5;
    const int wm   = wid >> 2;      // 0..1  (m offset wm*64)
    const int wn   = wid & 3;       // 0..3  (n offset wn*32)

    const int P0 = blockIdx.x * 128;
    const int b  = P0 >> 12;
    const int p0 = P0 & 4095;
    const int m0 = blockIdx.y * 128;

    const float* Ag = g_wA + (size_t)m0 * KCDIM;
    const float* Bg = g_samp + (size_t)(b * HW + p0) * KCDIM;

    const int lrow = tid >> 3;      // 0..31 loader row base (+32*it)
    const int lc4  = tid & 7;       // 0..7  loader float4 within 32-float chunk

    float acc[16][4];
#pragma unroll
    for (int i = 0; i < 16; i++)
#pragma unroll
        for (int j = 0; j < 4; j++) acc[i][j] = 0.0f;

    // prologue: chunk 0 -> stage 0
#pragma unroll
    for (int it = 0; it < 4; it++) {
        int row = lrow + it * 32;
        cp16(As_u + (row * ASTR + lc4 * 4) * 4, Ag + (size_t)row * KCDIM + lc4 * 4);
        cp16(Bs_u + (row * ASTR + lc4 * 4) * 4, Bg + (size_t)row * KCDIM + lc4 * 4);
    }
    CP_COMMIT();
    CP_WAIT0();
    __syncthreads();

    const int fr = lane >> 2;       // 0..7
    const int fc = lane & 3;        // 0..3

    for (int t = 0; t < KT; t++) {
        int cur = t & 1;
        if (t + 1 < KT) {
            int nxt = cur ^ 1;
            const float* Asrc = Ag + (t + 1) * 32;
            const float* Bsrc = Bg + (t + 1) * 32;
            uint32_t aD = As_u + nxt * TILE_F * 4;
            uint32_t bD = Bs_u + nxt * TILE_F * 4;
#pragma unroll
            for (int it = 0; it < 4; it++) {
                int row = lrow + it * 32;
                cp16(aD + (row * ASTR + lc4 * 4) * 4, Asrc + (size_t)row * KCDIM + lc4 * 4);
                cp16(bD + (row * ASTR + lc4 * 4) * 4, Bsrc + (size_t)row * KCDIM + lc4 * 4);
            }
            CP_COMMIT();
        }

        const float* Ab = As + cur * TILE_F + (wm * 64) * ASTR;
        const float* Bb = Bs + cur * TILE_F + (wn * 32) * ASTR;

#pragma unroll
        for (int ks = 0; ks < 4; ks++) {
            int k0 = ks * 8;
            uint32_t af[4][4];
#pragma unroll
            for (int mt = 0; mt < 4; mt++) {
                int r0 = mt * 16 + fr;
                af[mt][0] = __float_as_uint(Ab[r0 * ASTR + k0 + fc]);
                af[mt][1] = __float_as_uint(Ab[(r0 + 8) * ASTR + k0 + fc]);
                af[mt][2] = __float_as_uint(Ab[r0 * ASTR + k0 + fc + 4]);
                af[mt][3] = __float_as_uint(Ab[(r0 + 8) * ASTR + k0 + fc + 4]);
            }
            uint32_t bf[4][2];
#pragma unroll
            for (int nt = 0; nt < 4; nt++) {
                int c0 = nt * 8 + fr;
                bf[nt][0] = __float_as_uint(Bb[c0 * ASTR + k0 + fc]);
                bf[nt][1] = __float_as_uint(Bb[c0 * ASTR + k0 + fc + 4]);
            }
#pragma unroll
            for (int mt = 0; mt < 4; mt++)
#pragma unroll
                for (int nt = 0; nt < 4; nt++)
                    mma_tf32_16x8x8(acc[mt * 4 + nt], af[mt], bf[nt]);
        }

        if (t + 1 < KT) CP_WAIT0();
        __syncthreads();
    }

    // epilogue
    float* ob = out + ((size_t)b * COUT + m0 + wm * 64) * HW + p0 + wn * 32;
#pragma unroll
    for (int mt = 0; mt < 4; mt++) {
#pragma unroll
        for (int nt = 0; nt < 4; nt++) {
            float* d = acc[mt * 4 + nt];
            int row0 = mt * 16 + (lane >> 2);
            int col0 = nt * 8 + 2 * (lane & 3);
            *(float2*)(ob + (size_t)row0 * HW + col0)       = make_float2(d[0], d[1]);
            *(float2*)(ob + (size_t)(row0 + 8) * HW + col0) = make_float2(d[2], d[3]);
        }
    }
}

// ------------------------- kernel 6: GroupNorm stats -------------------------
__global__ void gn_stats_kernel(const float* __restrict__ out) {
    __shared__ float sh_s[256], sh_ss[256];
    int bg = blockIdx.x;
    const float4* src = (const float4*)(out + (size_t)bg * 8 * HW);
    float s = 0.f, ss = 0.f;
    for (int i = threadIdx.x; i < 8 * HW / 4; i += 256) {
        float4 v = src[i];
        s  += v.x + v.y + v.z + v.w;
        ss += v.x * v.x + v.y * v.y + v.z * v.z + v.w * v.w;
    }
    sh_s[threadIdx.x] = s;
    sh_ss[threadIdx.x] = ss;
    __syncthreads();
    for (int stride = 128; stride > 0; stride >>= 1) {
        if (threadIdx.x < stride) {
            sh_s[threadIdx.x]  += sh_s[threadIdx.x + stride];
            sh_ss[threadIdx.x] += sh_ss[threadIdx.x + stride];
        }
        __syncthreads();
    }
    if (threadIdx.x == 0) {
        const float inv_n = 1.0f / (8.0f * HW);
        float mu  = sh_s[0] * inv_n;
        float var = sh_ss[0] * inv_n - mu * mu;
        g_stats[bg * 2]     = mu;
        g_stats[bg * 2 + 1] = rsqrtf(var + EPSGN);
    }
}

// ------------------------- kernel 7: GroupNorm apply + ReLU ------------------
__global__ void gn_apply_kernel(float* __restrict__ out,
                                const float* __restrict__ gamma,
                                const float* __restrict__ beta) {
    int i = blockIdx.x * 256 + threadIdx.x;
    if (i >= BATCH * COUT * HW / 4) return;
    int base = i * 4;
    int bg = base / (8 * HW);
    int c  = (base >> 12) & 255;
    float mu   = g_stats[bg * 2];
    float rstd = g_stats[bg * 2 + 1];
    float gsc  = gamma[c] * rstd;
    float gbi  = beta[c] - mu * gsc;
    float4* p = (float4*)out + i;
    float4 v = *p;
    v.x = fmaxf(0.f, fmaf(v.x, gsc, gbi));
    v.y = fmaxf(0.f, fmaf(v.y, gsc, gbi));
    v.z = fmaxf(0.f, fmaf(v.z, gsc, gbi));
    v.w = fmaxf(0.f, fmaf(v.w, gsc, gbi));
    *p = v;
}

// ------------------------- launch -------------------------------------------
extern "C" void kernel_launch(void* const* d_in, const int* in_sizes, int n_in,
                              void* d_out, int out_size) {
    const float* x        = (const float*)d_in[0];
    const float* offset_w = (const float*)d_in[1];
    const float* offset_b = (const float*)d_in[2];
    const float* deform_w = (const float*)d_in[3];
    const float* gn_gamma = (const float*)d_in[4];
    const float* gn_beta  = (const float*)d_in[5];
    float* out = (float*)d_out;

    static bool configured = false;
    if (!configured) {
        cudaFuncSetAttribute(gemm_mma_kernel,
                             cudaFuncAttributeMaxDynamicSharedMemorySize, GEMM_SMEM);
        configured = true;
    }

    init_offsets_kernel<<<(BATCH * OFFCH * HW + 255) / 256, 256>>>(offset_b);
    offset_conv_kernel<<<512, 256>>>(x, offset_w);
    repack_w_kernel<<<((int)(COUT * KCDIM) + 255) / 256, 256>>>(deform_w);
    sample_kernel<<<BATCH * KTAPS * 128, 256>>>(x);
    {
        dim3 grid(BATCH * HW / 128, COUT / 128);
        gemm_mma_kernel<<<grid, 256, GEMM_SMEM>>>(out);
    }
    gn_stats_kernel<<<BATCH * GNG, 256>>>(out);
    gn_apply_kernel<<<(BATCH * COUT * HW / 4 + 255) / 256, 256>>>(out, gn_gamma, gn_beta);
}

// round 9
// speedup vs baseline: 2.0367x; 1.1556x over previous
#include <cuda_runtime.h>
#include <cuda_bf16.h>
#include <cstdint>

// Problem constants
#define BATCH 4
#define CIN   256
#define COUT  256
#define HH    64
#define WW    64
#define HW    4096
#define KTAPS 9
#define KCDIM 2304          // CIN * KTAPS
#define OFFCH 18
#define GNG   32
#define EPSGN 1e-5f

// ------------------------- helpers ------------------------------------------
__device__ __forceinline__ float to_tf32(float x) {
    float y;
    asm("cvt.rna.tf32.f32 %0, %1;" : "=f"(y) : "f"(x));
    return y;
}
__device__ __forceinline__ uint32_t smem_u32(const void* p) {
    uint32_t a;
    asm("{ .reg .u64 t; cvta.to.shared.u64 t, %1; cvt.u32.u64 %0, t; }" : "=r"(a) : "l"(p));
    return a;
}
__device__ __forceinline__ void cp16(uint32_t s, const void* g) {
    asm volatile("cp.async.cg.shared.global [%0], [%1], 16;" :: "r"(s), "l"(g));
}
#define CP_COMMIT() asm volatile("cp.async.commit_group;" ::: "memory")
#define CP_WAIT0()  asm volatile("cp.async.wait_group 0;" ::: "memory")

__device__ __forceinline__ void mma_tf32_16x8x8(float* d, const uint32_t* a, const uint32_t* b) {
    asm volatile(
        "mma.sync.aligned.m16n8k8.row.col.f32.tf32.tf32.f32 "
        "{%0,%1,%2,%3}, {%4,%5,%6,%7}, {%8,%9}, {%0,%1,%2,%3};"
        : "+f"(d[0]), "+f"(d[1]), "+f"(d[2]), "+f"(d[3])
        : "r"(a[0]), "r"(a[1]), "r"(a[2]), "r"(a[3]), "r"(b[0]), "r"(b[1]));
}

// ------------------------- device scratch ------------------------------------
__device__ float g_offsets[BATCH * OFFCH * HW];                 // 1.18 MB
__device__ float g_wA[(size_t)COUT * KCDIM];                    // [oc][k*256+c], tf32-rounded
__device__ float g_sparams[(size_t)BATCH * HW * KTAPS * 8];     // 4.7 MB: [b][p][tap][w00..w11,i00..i11]
__device__ float g_stats[BATCH * GNG * 2];

// ------------------------- kernel 1: init offsets with bias ------------------
__global__ void init_offsets_kernel(const float* __restrict__ ob) {
    int i = blockIdx.x * 256 + threadIdx.x;
    if (i < BATCH * OFFCH * HW) {
        int ch = (i >> 12) % OFFCH;
        g_offsets[i] = ob[ch];
    }
}

// ------------------------- kernel 2: offset conv (3x3, 256->18) --------------
__global__ void offset_conv_kernel(const float* __restrict__ x,
                                   const float* __restrict__ ow) {
    __shared__ float ws[OFFCH * 32 * 9];
    int g    = blockIdx.x >> 6;
    int tile = blockIdx.x & 63;
    int tid  = threadIdx.x;

    for (int i = tid; i < OFFCH * 32 * 9; i += 256) {
        int j  = i % 9;
        int t  = i / 9;
        int ci = t % 32;
        int ch = t / 32;
        ws[i] = ow[(ch * CIN + g * 32 + ci) * 9 + j];
    }
    __syncthreads();

    int P  = tile * 256 + tid;
    int b  = P >> 12;
    int p  = P & 4095;
    int y  = p >> 6;
    int xx = p & 63;

    int   off[9];
    float vmask[9];
#pragma unroll
    for (int ky = 0; ky < 3; ky++)
#pragma unroll
        for (int kx = 0; kx < 3; kx++) {
            int j  = ky * 3 + kx;
            int yy = y + ky - 1, xc = xx + kx - 1;
            vmask[j] = (yy >= 0 && yy < HH && xc >= 0 && xc < WW) ? 1.0f : 0.0f;
            off[j] = (ky - 1) * WW + (kx - 1);
        }

    float acc[OFFCH];
#pragma unroll
    for (int ch = 0; ch < OFFCH; ch++) acc[ch] = 0.0f;

    const float* xb = x + ((size_t)(b * CIN + g * 32)) * HW + p;
    for (int ci = 0; ci < 32; ci++) {
        const float* xc = xb + (size_t)ci * HW;
        float v[9];
#pragma unroll
        for (int j = 0; j < 9; j++)
            v[j] = (vmask[j] != 0.0f) ? xc[off[j]] : 0.0f;
#pragma unroll
        for (int ch = 0; ch < OFFCH; ch++) {
            const float* wc = &ws[(ch * 32 + ci) * 9];
            float a = acc[ch];
#pragma unroll
            for (int j = 0; j < 9; j++) a = fmaf(wc[j], v[j], a);
            acc[ch] = a;
        }
    }
#pragma unroll
    for (int ch = 0; ch < OFFCH; ch++)
        atomicAdd(&g_offsets[(b * OFFCH + ch) * HW + p], acc[ch]);
}

// ------------------------- kernel 3: repack weights (tf32-rounded) -----------
// deform_w[oc][c][k] -> wA[oc][k*256+c]
__global__ void repack_w_kernel(const float* __restrict__ dw) {
    int idx = blockIdx.x * 256 + threadIdx.x;
    if (idx < COUT * KCDIM) {
        int r  = idx % KCDIM;
        int oc = idx / KCDIM;
        int k  = r >> 8;
        int c  = r & 255;
        g_wA[idx] = to_tf32(dw[(size_t)oc * KCDIM + c * 9 + k]);
    }
}

// ------------------------- kernel 4: precompute bilinear params --------------
// One thread per (b, pixel): all 9 taps -> 72 contiguous floats. Coalesced.
__global__ void precompute_params_kernel() {
    int P = blockIdx.x * 256 + threadIdx.x;        // 0 .. 16383
    int b = P >> 12;
    int p = P & 4095;
    int y  = p >> 6;
    int xx = p & 63;
    float* o = g_sparams + (size_t)P * (KTAPS * 8);

#pragma unroll
    for (int k = 0; k < KTAPS; k++) {
        float dy = g_offsets[(b * OFFCH + 2 * k)     * HW + p];
        float dx = g_offsets[(b * OFFCH + 2 * k + 1) * HW + p];
        int ky = k / 3, kx = k % 3;

        float py = (float)(y - 1 + ky) + dy;
        float px = (float)(xx - 1 + kx) + dx;
        float fy = floorf(py), fx = floorf(px);
        float ty = py - fy,   tx = px - fx;
        int y0 = (int)fy, x0 = (int)fx;
        int y1 = y0 + 1,  x1 = x0 + 1;

        float w00 = (1.f - ty) * (1.f - tx);
        float w01 = (1.f - ty) * tx;
        float w10 = ty * (1.f - tx);
        float w11 = ty * tx;

        bool vy0 = (y0 >= 0 && y0 < HH), vy1 = (y1 >= 0 && y1 < HH);
        bool vx0 = (x0 >= 0 && x0 < WW), vx1 = (x1 >= 0 && x1 < WW);
        if (!(vy0 && vx0)) w00 = 0.f;
        if (!(vy0 && vx1)) w01 = 0.f;
        if (!(vy1 && vx0)) w10 = 0.f;
        if (!(vy1 && vx1)) w11 = 0.f;

        int yc0 = min(max(y0, 0), HH - 1), yc1 = min(max(y1, 0), HH - 1);
        int xc0 = min(max(x0, 0), WW - 1), xc1 = min(max(x1, 0), WW - 1);

        float4 wv = make_float4(w00, w01, w10, w11);
        float4 iv = make_float4(__int_as_float(yc0 * WW + xc0),
                                __int_as_float(yc0 * WW + xc1),
                                __int_as_float(yc1 * WW + xc0),
                                __int_as_float(yc1 * WW + xc1));
        *(float4*)(o + k * 8)     = wv;
        *(float4*)(o + k * 8 + 4) = iv;
    }
}

// ------------------------- kernel 5: FUSED sample + tf32 GEMM ----------------
// C[oc=128 (by)][p=128 (bx)] per CTA.  A = g_wA (K-major) via cp.async.
// B produced in-kernel: chunk t covers tap t/8, channels (t%8)*32..+32.
// Params cached in SMEM; per-thread: 1 pixel x 16 channels, 4 gathers each.
#define ASTR 36                     // padded row stride (floats)
#define TILE_F (128 * ASTR)         // floats per (stage, matrix)
#define PSTR 76                     // padded param row stride (floats, multiple of 4!)
#define PARAM_F (128 * PSTR)        // 9728 floats
#define FUSE_SMEM ((PARAM_F + 4 * TILE_F) * 4)   // 112640 B
#define KT 72

__global__ void __launch_bounds__(256, 2) fused_gemm_kernel(const float* __restrict__ x,
                                                            float* __restrict__ out) {
    extern __shared__ float sm[];
    float* sp = sm;                       // params [128 px][PSTR]
    float* As = sm + PARAM_F;             // [2][128][ASTR]
    float* Bs = As + 2 * TILE_F;          // [2][128][ASTR]
    uint32_t As_u = smem_u32(As);

    const int tid  = threadIdx.x;
    const int lane = tid & 31;
    const int wid  = tid >> 5;
    const int wm   = wid >> 2;
    const int wn   = wid & 3;

    const int P0 = blockIdx.x * 128;
    const int b  = P0 >> 12;
    const int p0 = P0 & 4095;
    const int m0 = blockIdx.y * 128;

    const float* Ag = g_wA + (size_t)m0 * KCDIM;
    const float* xb = x + (size_t)b * CIN * HW;

    // producer assignment: 1 pixel x 16 channels per thread
    const int ppx   = tid & 127;
    const int phalf = tid >> 7;           // 0: ch 0-15, 1: ch 16-31

    // ---- load params into smem (72 floats per pixel, padded to 76) ----
    {
        const float4* gp = (const float4*)(g_sparams + ((size_t)b * HW + p0) * (KTAPS * 8));
#pragma unroll
        for (int n = 0; n < 9; n++) {
            int i = tid + n * 256;                 // 0..2303 float4s
            float4 f = gp[i];
            int L  = i * 4;
            int px = L / 72;
            int rem = L - px * 72;
            *(float4*)&sp[px * PSTR + rem] = f;
        }
    }

    // ---- A chunk 0 via cp.async ----
    const int lrow = tid >> 3;
    const int lc4  = tid & 7;
#pragma unroll
    for (int it = 0; it < 4; it++) {
        int row = lrow + it * 32;
        cp16(As_u + (row * ASTR + lc4 * 4) * 4, Ag + (size_t)row * KCDIM + lc4 * 4);
    }
    CP_COMMIT();
    __syncthreads();                      // params visible

    // ---- produce B chunk 0 (tap 0, channels phalf*16..+16) ----
    {
        float4 pa = *(float4*)&sp[ppx * PSTR];      // tap 0 weights
        float4 pb = *(float4*)&sp[ppx * PSTR + 4];  // tap 0 indices
        int i00 = __float_as_int(pb.x), i01 = __float_as_int(pb.y);
        int i10 = __float_as_int(pb.z), i11 = __float_as_int(pb.w);
        const float* bx = xb + (size_t)(phalf * 16) * HW;
        float* Bw = Bs + ppx * ASTR + phalf * 16;
#pragma unroll
        for (int ks = 0; ks < 4; ks++) {
            float rv[4][4];
#pragma unroll
            for (int j = 0; j < 4; j++) {
                const float* bc = bx + (size_t)(ks * 4 + j) * HW;
                rv[j][0] = bc[i00]; rv[j][1] = bc[i01];
                rv[j][2] = bc[i10]; rv[j][3] = bc[i11];
            }
            float4 o;
            o.x = to_tf32(pa.x * rv[0][0] + pa.y * rv[0][1] + pa.z * rv[0][2] + pa.w * rv[0][3]);
            o.y = to_tf32(pa.x * rv[1][0] + pa.y * rv[1][1] + pa.z * rv[1][2] + pa.w * rv[1][3]);
            o.z = to_tf32(pa.x * rv[2][0] + pa.y * rv[2][1] + pa.z * rv[2][2] + pa.w * rv[2][3]);
            o.w = to_tf32(pa.x * rv[3][0] + pa.y * rv[3][1] + pa.z * rv[3][2] + pa.w * rv[3][3]);
            *(float4*)&Bw[ks * 4] = o;
        }
    }
    CP_WAIT0();
    __syncthreads();

    float acc[16][4];
#pragma unroll
    for (int i = 0; i < 16; i++)
#pragma unroll
        for (int j = 0; j < 4; j++) acc[i][j] = 0.0f;

    const int fr = lane >> 2;
    const int fc = lane & 3;

    for (int t = 0; t < KT; t++) {
        int cur = t & 1;
        int nxt = cur ^ 1;
        bool hasN = (t + 1 < KT);

        if (hasN) {
            const float* Asrc = Ag + (t + 1) * 32;
            uint32_t aD = As_u + nxt * TILE_F * 4;
#pragma unroll
            for (int it = 0; it < 4; it++) {
                int row = lrow + it * 32;
                cp16(aD + (row * ASTR + lc4 * 4) * 4, Asrc + (size_t)row * KCDIM + lc4 * 4);
            }
            CP_COMMIT();
        }

        // params + base for B(t+1)
        float4 pa;
        int i00 = 0, i01 = 0, i10 = 0, i11 = 0;
        const float* bx = xb;
        float* Bw = Bs + nxt * TILE_F + ppx * ASTR + phalf * 16;
        if (hasN) {
            int t1  = t + 1;
            int kt1 = t1 >> 3;
            int cb1 = ((t1 & 7) << 5) + phalf * 16;
            pa = *(float4*)&sp[ppx * PSTR + kt1 * 8];
            float4 pb = *(float4*)&sp[ppx * PSTR + kt1 * 8 + 4];
            i00 = __float_as_int(pb.x); i01 = __float_as_int(pb.y);
            i10 = __float_as_int(pb.z); i11 = __float_as_int(pb.w);
            bx = xb + (size_t)cb1 * HW;
        }

        const float* Ab = As + cur * TILE_F + (wm * 64) * ASTR;
        const float* Bb = Bs + cur * TILE_F + (wn * 32) * ASTR;

#pragma unroll
        for (int ks = 0; ks < 4; ks++) {
            // issue gathers for B(t+1), group ks (4 channels x 4 corners)
            float rv[4][4];
            if (hasN) {
#pragma unroll
                for (int j = 0; j < 4; j++) {
                    const float* bc = bx + (size_t)(ks * 4 + j) * HW;
                    rv[j][0] = bc[i00]; rv[j][1] = bc[i01];
                    rv[j][2] = bc[i10]; rv[j][3] = bc[i11];
                }
            }

            // MMA sub-chunk ks on current stage
            int k0 = ks * 8;
            uint32_t af[4][4];
#pragma unroll
            for (int mt = 0; mt < 4; mt++) {
                int r0 = mt * 16 + fr;
                af[mt][0] = __float_as_uint(Ab[r0 * ASTR + k0 + fc]);
                af[mt][1] = __float_as_uint(Ab[(r0 + 8) * ASTR + k0 + fc]);
                af[mt][2] = __float_as_uint(Ab[r0 * ASTR + k0 + fc + 4]);
                af[mt][3] = __float_as_uint(Ab[(r0 + 8) * ASTR + k0 + fc + 4]);
            }
            uint32_t bf[4][2];
#pragma unroll
            for (int nt = 0; nt < 4; nt++) {
                int c0 = nt * 8 + fr;
                bf[nt][0] = __float_as_uint(Bb[c0 * ASTR + k0 + fc]);
                bf[nt][1] = __float_as_uint(Bb[c0 * ASTR + k0 + fc + 4]);
            }
#pragma unroll
            for (int mt = 0; mt < 4; mt++)
#pragma unroll
                for (int nt = 0; nt < 4; nt++)
                    mma_tf32_16x8x8(acc[mt * 4 + nt], af[mt], bf[nt]);

            // combine + store B(t+1), group ks
            if (hasN) {
                float4 o;
                o.x = to_tf32(pa.x * rv[0][0] + pa.y * rv[0][1] + pa.z * rv[0][2] + pa.w * rv[0][3]);
                o.y = to_tf32(pa.x * rv[1][0] + pa.y * rv[1][1] + pa.z * rv[1][2] + pa.w * rv[1][3]);
                o.z = to_tf32(pa.x * rv[2][0] + pa.y * rv[2][1] + pa.z * rv[2][2] + pa.w * rv[2][3]);
                o.w = to_tf32(pa.x * rv[3][0] + pa.y * rv[3][1] + pa.z * rv[3][2] + pa.w * rv[3][3]);
                *(float4*)&Bw[ks * 4] = o;
            }
        }

        if (hasN) CP_WAIT0();
        __syncthreads();
    }

    // epilogue
    float* ob = out + ((size_t)b * COUT + m0 + wm * 64) * HW + p0 + wn * 32;
#pragma unroll
    for (int mt = 0; mt < 4; mt++) {
#pragma unroll
        for (int nt = 0; nt < 4; nt++) {
            float* d = acc[mt * 4 + nt];
            int row0 = mt * 16 + (lane >> 2);
            int col0 = nt * 8 + 2 * (lane & 3);
            *(float2*)(ob + (size_t)row0 * HW + col0)       = make_float2(d[0], d[1]);
            *(float2*)(ob + (size_t)(row0 + 8) * HW + col0) = make_float2(d[2], d[3]);
        }
    }
}

// ------------------------- kernel 6: GroupNorm stats -------------------------
__global__ void gn_stats_kernel(const float* __restrict__ out) {
    __shared__ float sh_s[256], sh_ss[256];
    int bg = blockIdx.x;
    const float4* src = (const float4*)(out + (size_t)bg * 8 * HW);
    float s = 0.f, ss = 0.f;
    for (int i = threadIdx.x; i < 8 * HW / 4; i += 256) {
        float4 v = src[i];
        s  += v.x + v.y + v.z + v.w;
        ss += v.x * v.x + v.y * v.y + v.z * v.z + v.w * v.w;
    }
    sh_s[threadIdx.x] = s;
    sh_ss[threadIdx.x] = ss;
    __syncthreads();
    for (int stride = 128; stride > 0; stride >>= 1) {
        if (threadIdx.x < stride) {
            sh_s[threadIdx.x]  += sh_s[threadIdx.x + stride];
            sh_ss[threadIdx.x] += sh_ss[threadIdx.x + stride];
        }
        __syncthreads();
    }
    if (threadIdx.x == 0) {
        const float inv_n = 1.0f / (8.0f * HW);
        float mu  = sh_s[0] * inv_n;
        float var = sh_ss[0] * inv_n - mu * mu;
        g_stats[bg * 2]     = mu;
        g_stats[bg * 2 + 1] = rsqrtf(var + EPSGN);
    }
}

// ------------------------- kernel 7: GroupNorm apply + ReLU ------------------
__global__ void gn_apply_kernel(float* __restrict__ out,
                                const float* __restrict__ gamma,
                                const float* __restrict__ beta) {
    int i = blockIdx.x * 256 + threadIdx.x;
    if (i >= BATCH * COUT * HW / 4) return;
    int base = i * 4;
    int bg = base / (8 * HW);
    int c  = (base >> 12) & 255;
    float mu   = g_stats[bg * 2];
    float rstd = g_stats[bg * 2 + 1];
    float gsc  = gamma[c] * rstd;
    float gbi  = beta[c] - mu * gsc;
    float4* p = (float4*)out + i;
    float4 v = *p;
    v.x = fmaxf(0.f, fmaf(v.x, gsc, gbi));
    v.y = fmaxf(0.f, fmaf(v.y, gsc, gbi));
    v.z = fmaxf(0.f, fmaf(v.z, gsc, gbi));
    v.w = fmaxf(0.f, fmaf(v.w, gsc, gbi));
    *p = v;
}

// ------------------------- launch -------------------------------------------
extern "C" void kernel_launch(void* const* d_in, const int* in_sizes, int n_in,
                              void* d_out, int out_size) {
    const float* x        = (const float*)d_in[0];
    const float* offset_w = (const float*)d_in[1];
    const float* offset_b = (const float*)d_in[2];
    const float* deform_w = (const float*)d_in[3];
    const float* gn_gamma = (const float*)d_in[4];
    const float* gn_beta  = (const float*)d_in[5];
    float* out = (float*)d_out;

    static bool configured = false;
    if (!configured) {
        cudaFuncSetAttribute(fused_gemm_kernel,
                             cudaFuncAttributeMaxDynamicSharedMemorySize, FUSE_SMEM);
        configured = true;
    }

    init_offsets_kernel<<<(BATCH * OFFCH * HW + 255) / 256, 256>>>(offset_b);
    offset_conv_kernel<<<512, 256>>>(x, offset_w);
    repack_w_kernel<<<((int)(COUT * KCDIM) + 255) / 256, 256>>>(deform_w);
    precompute_params_kernel<<<BATCH * HW / 256, 256>>>();
    {
        dim3 grid(BATCH * HW / 128, COUT / 128);
        fused_gemm_kernel<<<grid, 256, FUSE_SMEM>>>(x, out);
    }
    gn_stats_kernel<<<BATCH * GNG, 256>>>(out);
    gn_apply_kernel<<<(BATCH * COUT * HW / 4 + 255) / 256, 256>>>(out, gn_gamma, gn_beta);
}

// round 12
// speedup vs baseline: 2.2629x; 1.1111x over previous
#include <cuda_runtime.h>
#include <cuda_bf16.h>
#include <cstdint>

// Problem constants
#define BATCH 4
#define CIN   256
#define COUT  256
#define HH    64
#define WW    64
#define HW    4096
#define KTAPS 9
#define KCDIM 2304          // CIN * KTAPS
#define OFFCH 18
#define GNG   32
#define EPSGN 1e-5f

// ------------------------- helpers ------------------------------------------
__device__ __forceinline__ float to_tf32(float x) {
    float y;
    asm("cvt.rna.tf32.f32 %0, %1;" : "=f"(y) : "f"(x));
    return y;
}
__device__ __forceinline__ uint32_t smem_u32(const void* p) {
    uint32_t a;
    asm("{ .reg .u64 t; cvta.to.shared.u64 t, %1; cvt.u32.u64 %0, t; }" : "=r"(a) : "l"(p));
    return a;
}
__device__ __forceinline__ void cp16(uint32_t s, const void* g) {
    asm volatile("cp.async.cg.shared.global [%0], [%1], 16;" :: "r"(s), "l"(g));
}
#define CP_COMMIT() asm volatile("cp.async.commit_group;" ::: "memory")
#define CP_WAIT0()  asm volatile("cp.async.wait_group 0;" ::: "memory")

__device__ __forceinline__ void mma_tf32_16x8x8(float* d, const uint32_t* a, const uint32_t* b) {
    asm volatile(
        "mma.sync.aligned.m16n8k8.row.col.f32.tf32.tf32.f32 "
        "{%0,%1,%2,%3}, {%4,%5,%6,%7}, {%8,%9}, {%0,%1,%2,%3};"
        : "+f"(d[0]), "+f"(d[1]), "+f"(d[2]), "+f"(d[3])
        : "r"(a[0]), "r"(a[1]), "r"(a[2]), "r"(a[3]), "r"(b[0]), "r"(b[1]));
}

// ------------------------- device scratch ------------------------------------
__device__ float g_offsets[BATCH * OFFCH * HW];                 // 1.18 MB
__device__ float g_wA[(size_t)COUT * KCDIM];                    // [oc][k*256+c], tf32-rounded
__device__ float g_sparams[(size_t)BATCH * HW * KTAPS * 8];     // 4.7 MB
__device__ float g_stats[BATCH * GNG * 2];

// ------------------------- kernel 1: init offsets with bias ------------------
__global__ void init_offsets_kernel(const float* __restrict__ ob) {
    int i = blockIdx.x * 256 + threadIdx.x;
    if (i < BATCH * OFFCH * HW) {
        int ch = (i >> 12) % OFFCH;
        g_offsets[i] = ob[ch];
    }
}

// ------------------------- kernel 2: offset conv (3x3, 256->18) --------------
__global__ void offset_conv_kernel(const float* __restrict__ x,
                                   const float* __restrict__ ow) {
    __shared__ float ws[OFFCH * 32 * 9];
    int g    = blockIdx.x >> 6;
    int tile = blockIdx.x & 63;
    int tid  = threadIdx.x;

    for (int i = tid; i < OFFCH * 32 * 9; i += 256) {
        int j  = i % 9;
        int t  = i / 9;
        int ci = t % 32;
        int ch = t / 32;
        ws[i] = ow[(ch * CIN + g * 32 + ci) * 9 + j];
    }
    __syncthreads();

    int P  = tile * 256 + tid;
    int b  = P >> 12;
    int p  = P & 4095;
    int y  = p >> 6;
    int xx = p & 63;

    int   off[9];
    float vmask[9];
#pragma unroll
    for (int ky = 0; ky < 3; ky++)
#pragma unroll
        for (int kx = 0; kx < 3; kx++) {
            int j  = ky * 3 + kx;
            int yy = y + ky - 1, xc = xx + kx - 1;
            vmask[j] = (yy >= 0 && yy < HH && xc >= 0 && xc < WW) ? 1.0f : 0.0f;
            off[j] = (ky - 1) * WW + (kx - 1);
        }

    float acc[OFFCH];
#pragma unroll
    for (int ch = 0; ch < OFFCH; ch++) acc[ch] = 0.0f;

    const float* xb = x + ((size_t)(b * CIN + g * 32)) * HW + p;
    for (int ci = 0; ci < 32; ci++) {
        const float* xc = xb + (size_t)ci * HW;
        float v[9];
#pragma unroll
        for (int j = 0; j < 9; j++)
            v[j] = (vmask[j] != 0.0f) ? xc[off[j]] : 0.0f;
#pragma unroll
        for (int ch = 0; ch < OFFCH; ch++) {
            const float* wc = &ws[(ch * 32 + ci) * 9];
            float a = acc[ch];
#pragma unroll
            for (int j = 0; j < 9; j++) a = fmaf(wc[j], v[j], a);
            acc[ch] = a;
        }
    }
#pragma unroll
    for (int ch = 0; ch < OFFCH; ch++)
        atomicAdd(&g_offsets[(b * OFFCH + ch) * HW + p], acc[ch]);
}

// ------------------------- kernel 3: repack weights (tf32-rounded) -----------
__global__ void repack_w_kernel(const float* __restrict__ dw) {
    int idx = blockIdx.x * 256 + threadIdx.x;
    if (idx < COUT * KCDIM) {
        int r  = idx % KCDIM;
        int oc = idx / KCDIM;
        int k  = r >> 8;
        int c  = r & 255;
        g_wA[idx] = to_tf32(dw[(size_t)oc * KCDIM + c * 9 + k]);
    }
}

// ------------------------- kernel 4: precompute bilinear params --------------
__global__ void precompute_params_kernel() {
    int P = blockIdx.x * 256 + threadIdx.x;        // 0 .. 16383
    int b = P >> 12;
    int p = P & 4095;
    int y  = p >> 6;
    int xx = p & 63;
    float* o = g_sparams + (size_t)P * (KTAPS * 8);

#pragma unroll
    for (int k = 0; k < KTAPS; k++) {
        float dy = g_offsets[(b * OFFCH + 2 * k)     * HW + p];
        float dx = g_offsets[(b * OFFCH + 2 * k + 1) * HW + p];
        int ky = k / 3, kx = k % 3;

        float py = (float)(y - 1 + ky) + dy;
        float px = (float)(xx - 1 + kx) + dx;
        float fy = floorf(py), fx = floorf(px);
        float ty = py - fy,   tx = px - fx;
        int y0 = (int)fy, x0 = (int)fx;
        int y1 = y0 + 1,  x1 = x0 + 1;

        float w00 = (1.f - ty) * (1.f - tx);
        float w01 = (1.f - ty) * tx;
        float w10 = ty * (1.f - tx);
        float w11 = ty * tx;

        bool vy0 = (y0 >= 0 && y0 < HH), vy1 = (y1 >= 0 && y1 < HH);
        bool vx0 = (x0 >= 0 && x0 < WW), vx1 = (x1 >= 0 && x1 < WW);
        if (!(vy0 && vx0)) w00 = 0.f;
        if (!(vy0 && vx1)) w01 = 0.f;
        if (!(vy1 && vx0)) w10 = 0.f;
        if (!(vy1 && vx1)) w11 = 0.f;

        int yc0 = min(max(y0, 0), HH - 1), yc1 = min(max(y1, 0), HH - 1);
        int xc0 = min(max(x0, 0), WW - 1), xc1 = min(max(x1, 0), WW - 1);

        float4 wv = make_float4(w00, w01, w10, w11);
        float4 iv = make_float4(__int_as_float(yc0 * WW + xc0),
                                __int_as_float(yc0 * WW + xc1),
                                __int_as_float(yc1 * WW + xc0),
                                __int_as_float(yc1 * WW + xc1));
        *(float4*)(o + k * 8)     = wv;
        *(float4*)(o + k * 8 + 4) = iv;
    }
}

// ------------------------- kernel 5: FUSED sample + tf32 GEMM ----------------
// One CTA: C[oc=256][p=128], 512 threads (16 warps = 4m x 4n).  Grid = 128.
// A = full g_wA via cp.async (256 rows/chunk).  B produced once per CTA:
// each thread gathers 1 pixel x 8 channels x 4 corners.
#define ASTR 36                     // padded row stride (floats)
#define TILE_AF (256 * ASTR)        // A floats per stage
#define TILE_BF (128 * ASTR)        // B floats per stage
#define PSTR 76                     // padded param row stride (multiple of 4)
#define PARAM_F (128 * PSTR)
#define FUSE_SMEM ((PARAM_F + 2 * TILE_AF + 2 * TILE_BF) * 4)   // 149504 B
#define KT 72

__global__ void __launch_bounds__(512, 1) fused_gemm_kernel(const float* __restrict__ x,
                                                            float* __restrict__ out) {
    extern __shared__ float sm[];
    float* sp = sm;                       // params [128 px][PSTR]
    float* As = sm + PARAM_F;             // [2][256][ASTR]
    float* Bs = As + 2 * TILE_AF;         // [2][128][ASTR]
    uint32_t As_u = smem_u32(As);

    const int tid  = threadIdx.x;
    const int lane = tid & 31;
    const int wid  = tid >> 5;
    const int wm   = wid >> 2;            // 0..3  (m offset wm*64)
    const int wn   = wid & 3;             // 0..3  (n offset wn*32)

    const int P0 = blockIdx.x * 128;
    const int b  = P0 >> 12;
    const int p0 = P0 & 4095;

    const float* Ag = g_wA;
    const float* xb = x + (size_t)b * CIN * HW;

    // producer assignment: 1 pixel x 8 channels per thread
    const int ppx = tid & 127;
    const int pq  = tid >> 7;             // 0..3 : channel octet pq*8..+8

    // ---- load params into smem (72 floats per pixel, padded to 76) ----
    {
        const float4* gp = (const float4*)(g_sparams + ((size_t)b * HW + p0) * (KTAPS * 8));
#pragma unroll
        for (int n = 0; n < 5; n++) {
            int i = tid + n * 512;                 // 0..2303 float4s
            if (i < 2304) {
                float4 f = gp[i];
                int L  = i * 4;
                int px = L / 72;
                int rem = L - px * 72;
                *(float4*)&sp[px * PSTR + rem] = f;
            }
        }
    }

    // ---- A chunk 0 via cp.async (256 rows x 32 floats) ----
    const int lrow = tid >> 3;            // 0..63 (+64*it)
    const int lc4  = tid & 7;
#pragma unroll
    for (int it = 0; it < 4; it++) {
        int row = lrow + it * 64;
        cp16(As_u + (row * ASTR + lc4 * 4) * 4, Ag + (size_t)row * KCDIM + lc4 * 4);
    }
    CP_COMMIT();
    __syncthreads();                      // params visible

    // ---- produce B chunk 0 (tap 0, channels pq*8..+8) ----
    {
        float4 pa = *(float4*)&sp[ppx * PSTR];
        float4 pb = *(float4*)&sp[ppx * PSTR + 4];
        int i00 = __float_as_int(pb.x), i01 = __float_as_int(pb.y);
        int i10 = __float_as_int(pb.z), i11 = __float_as_int(pb.w);
        const float* bx = xb + (size_t)(pq * 8) * HW;
        float* Bw = Bs + ppx * ASTR + pq * 8;
#pragma unroll
        for (int g = 0; g < 2; g++) {
            float rv[4][4];
#pragma unroll
            for (int j = 0; j < 4; j++) {
                const float* bc = bx + (size_t)(g * 4 + j) * HW;
                rv[j][0] = bc[i00]; rv[j][1] = bc[i01];
                rv[j][2] = bc[i10]; rv[j][3] = bc[i11];
            }
            float4 o;
            o.x = to_tf32(pa.x * rv[0][0] + pa.y * rv[0][1] + pa.z * rv[0][2] + pa.w * rv[0][3]);
            o.y = to_tf32(pa.x * rv[1][0] + pa.y * rv[1][1] + pa.z * rv[1][2] + pa.w * rv[1][3]);
            o.z = to_tf32(pa.x * rv[2][0] + pa.y * rv[2][1] + pa.z * rv[2][2] + pa.w * rv[2][3]);
            o.w = to_tf32(pa.x * rv[3][0] + pa.y * rv[3][1] + pa.z * rv[3][2] + pa.w * rv[3][3]);
            *(float4*)&Bw[g * 4] = o;
        }
    }
    CP_WAIT0();
    __syncthreads();

    float acc[16][4];
#pragma unroll
    for (int i = 0; i < 16; i++)
#pragma unroll
        for (int j = 0; j < 4; j++) acc[i][j] = 0.0f;

    const int fr = lane >> 2;
    const int fc = lane & 3;

    for (int t = 0; t < KT; t++) {
        int cur = t & 1;
        int nxt = cur ^ 1;
        bool hasN = (t + 1 < KT);

        if (hasN) {
            const float* Asrc = Ag + (t + 1) * 32;
            uint32_t aD = As_u + nxt * TILE_AF * 4;
#pragma unroll
            for (int it = 0; it < 4; it++) {
                int row = lrow + it * 64;
                cp16(aD + (row * ASTR + lc4 * 4) * 4, Asrc + (size_t)row * KCDIM + lc4 * 4);
            }
            CP_COMMIT();
        }

        // params + base for B(t+1)
        float4 pa;
        int i00 = 0, i01 = 0, i10 = 0, i11 = 0;
        const float* bx = xb;
        float* Bw = Bs + nxt * TILE_BF + ppx * ASTR + pq * 8;
        if (hasN) {
            int t1  = t + 1;
            int kt1 = t1 >> 3;
            int cb1 = ((t1 & 7) << 5) + pq * 8;
            pa = *(float4*)&sp[ppx * PSTR + kt1 * 8];
            float4 pb = *(float4*)&sp[ppx * PSTR + kt1 * 8 + 4];
            i00 = __float_as_int(pb.x); i01 = __float_as_int(pb.y);
            i10 = __float_as_int(pb.z); i11 = __float_as_int(pb.w);
            bx = xb + (size_t)cb1 * HW;
        }

        const float* Ab = As + cur * TILE_AF + (wm * 64) * ASTR;
        const float* Bb = Bs + cur * TILE_BF + (wn * 32) * ASTR;

#pragma unroll
        for (int ks = 0; ks < 4; ks++) {
            // issue gathers for B(t+1): groups 0,1 only (8 channels/thread)
            float rv[4][4];
            bool prod = hasN && (ks < 2);
            if (prod) {
#pragma unroll
                for (int j = 0; j < 4; j++) {
                    const float* bc = bx + (size_t)(ks * 4 + j) * HW;
                    rv[j][0] = bc[i00]; rv[j][1] = bc[i01];
                    rv[j][2] = bc[i10]; rv[j][3] = bc[i11];
                }
            }

            // MMA sub-chunk ks on current stage
            int k0 = ks * 8;
            uint32_t af[4][4];
#pragma unroll
            for (int mt = 0; mt < 4; mt++) {
                int r0 = mt * 16 + fr;
                af[mt][0] = __float_as_uint(Ab[r0 * ASTR + k0 + fc]);
                af[mt][1] = __float_as_uint(Ab[(r0 + 8) * ASTR + k0 + fc]);
                af[mt][2] = __float_as_uint(Ab[r0 * ASTR + k0 + fc + 4]);
                af[mt][3] = __float_as_uint(Ab[(r0 + 8) * ASTR + k0 + fc + 4]);
            }
            uint32_t bf[4][2];
#pragma unroll
            for (int nt = 0; nt < 4; nt++) {
                int c0 = nt * 8 + fr;
                bf[nt][0] = __float_as_uint(Bb[c0 * ASTR + k0 + fc]);
                bf[nt][1] = __float_as_uint(Bb[c0 * ASTR + k0 + fc + 4]);
            }
#pragma unroll
            for (int mt = 0; mt < 4; mt++)
#pragma unroll
                for (int nt = 0; nt < 4; nt++)
                    mma_tf32_16x8x8(acc[mt * 4 + nt], af[mt], bf[nt]);

            // combine + store B(t+1)
            if (prod) {
                float4 o;
                o.x = to_tf32(pa.x * rv[0][0] + pa.y * rv[0][1] + pa.z * rv[0][2] + pa.w * rv[0][3]);
                o.y = to_tf32(pa.x * rv[1][0] + pa.y * rv[1][1] + pa.z * rv[1][2] + pa.w * rv[1][3]);
                o.z = to_tf32(pa.x * rv[2][0] + pa.y * rv[2][1] + pa.z * rv[2][2] + pa.w * rv[2][3]);
                o.w = to_tf32(pa.x * rv[3][0] + pa.y * rv[3][1] + pa.z * rv[3][2] + pa.w * rv[3][3]);
                *(float4*)&Bw[ks * 4] = o;
            }
        }

        if (hasN) CP_WAIT0();
        __syncthreads();
    }

    // epilogue
    float* ob = out + ((size_t)b * COUT + wm * 64) * HW + p0 + wn * 32;
#pragma unroll
    for (int mt = 0; mt < 4; mt++) {
#pragma unroll
        for (int nt = 0; nt < 4; nt++) {
            float* d = acc[mt * 4 + nt];
            int row0 = mt * 16 + (lane >> 2);
            int col0 = nt * 8 + 2 * (lane & 3);
            *(float2*)(ob + (size_t)row0 * HW + col0)       = make_float2(d[0], d[1]);
            *(float2*)(ob + (size_t)(row0 + 8) * HW + col0) = make_float2(d[2], d[3]);
        }
    }
}

// ------------------------- kernel 6: GroupNorm stats -------------------------
__global__ void gn_stats_kernel(const float* __restrict__ out) {
    __shared__ float sh_s[256], sh_ss[256];
    int bg = blockIdx.x;
    const float4* src = (const float4*)(out + (size_t)bg * 8 * HW);
    float s = 0.f, ss = 0.f;
    for (int i = threadIdx.x; i < 8 * HW / 4; i += 256) {
        float4 v = src[i];
        s  += v.x + v.y + v.z + v.w;
        ss += v.x * v.x + v.y * v.y + v.z * v.z + v.w * v.w;
    }
    sh_s[threadIdx.x] = s;
    sh_ss[threadIdx.x] = ss;
    __syncthreads();
    for (int stride = 128; stride > 0; stride >>= 1) {
        if (threadIdx.x < stride) {
            sh_s[threadIdx.x]  += sh_s[threadIdx.x + stride];
            sh_ss[threadIdx.x] += sh_ss[threadIdx.x + stride];
        }
        __syncthreads();
    }
    if (threadIdx.x == 0) {
        const float inv_n = 1.0f / (8.0f * HW);
        float mu  = sh_s[0] * inv_n;
        float var = sh_ss[0] * inv_n - mu * mu;
        g_stats[bg * 2]     = mu;
        g_stats[bg * 2 + 1] = rsqrtf(var + EPSGN);
    }
}

// ------------------------- kernel 7: GroupNorm apply + ReLU ------------------
__global__ void gn_apply_kernel(float* __restrict__ out,
                                const float* __restrict__ gamma,
                                const float* __restrict__ beta) {
    int i = blockIdx.x * 256 + threadIdx.x;
    if (i >= BATCH * COUT * HW / 4) return;
    int base = i * 4;
    int bg = base / (8 * HW);
    int c  = (base >> 12) & 255;
    float mu   = g_stats[bg * 2];
    float rstd = g_stats[bg * 2 + 1];
    float gsc  = gamma[c] * rstd;
    float gbi  = beta[c] - mu * gsc;
    float4* p = (float4*)out + i;
    float4 v = *p;
    v.x = fmaxf(0.f, fmaf(v.x, gsc, gbi));
    v.y = fmaxf(0.f, fmaf(v.y, gsc, gbi));
    v.z = fmaxf(0.f, fmaf(v.z, gsc, gbi));
    v.w = fmaxf(0.f, fmaf(v.w, gsc, gbi));
    *p = v;
}

// ------------------------- launch -------------------------------------------
extern "C" void kernel_launch(void* const* d_in, const int* in_sizes, int n_in,
                              void* d_out, int out_size) {
    const float* x        = (const float*)d_in[0];
    const float* offset_w = (const float*)d_in[1];
    const float* offset_b = (const float*)d_in[2];
    const float* deform_w = (const float*)d_in[3];
    const float* gn_gamma = (const float*)d_in[4];
    const float* gn_beta  = (const float*)d_in[5];
    float* out = (float*)d_out;

    static bool configured = false;
    if (!configured) {
        cudaFuncSetAttribute(fused_gemm_kernel,
                             cudaFuncAttributeMaxDynamicSharedMemorySize, FUSE_SMEM);
        configured = true;
    }

    init_offsets_kernel<<<(BATCH * OFFCH * HW + 255) / 256, 256>>>(offset_b);
    offset_conv_kernel<<<512, 256>>>(x, offset_w);
    repack_w_kernel<<<((int)(COUT * KCDIM) + 255) / 256, 256>>>(deform_w);
    precompute_params_kernel<<<BATCH * HW / 256, 256>>>();
    fused_gemm_kernel<<<BATCH * HW / 128, 512, FUSE_SMEM>>>(x, out);
    gn_stats_kernel<<<BATCH * GNG, 256>>>(out);
    gn_apply_kernel<<<(BATCH * COUT * HW / 4 + 255) / 256, 256>>>(out, gn_gamma, gn_beta);
}

// round 16
// speedup vs baseline: 2.7382x; 1.2100x over previous
#include <cuda_runtime.h>
#include <cuda_bf16.h>
#include <cuda_fp16.h>
#include <cstdint>

// Problem constants
#define BATCH 4
#define CIN   256
#define COUT  256
#define HH    64
#define WW    64
#define HW    4096
#define KTAPS 9
#define KCDIM 2304          // CIN * KTAPS
#define OFFCH 18
#define GNG   32
#define EPSGN 1e-5f

// ------------------------- helpers ------------------------------------------
__device__ __forceinline__ uint32_t smem_u32(const void* p) {
    uint32_t a;
    asm("{ .reg .u64 t; cvta.to.shared.u64 t, %1; cvt.u32.u64 %0, t; }" : "=r"(a) : "l"(p));
    return a;
}
__device__ __forceinline__ void cp16(uint32_t s, const void* g) {
    asm volatile("cp.async.cg.shared.global [%0], [%1], 16;" :: "r"(s), "l"(g));
}
#define CP_COMMIT() asm volatile("cp.async.commit_group;" ::: "memory")
#define CP_WAIT0()  asm volatile("cp.async.wait_group 0;" ::: "memory")

// fp16 MMA, fp32 accumulate: D(16x8) += A(16x16) * B(16x8)
__device__ __forceinline__ void mma_f16_16x8x16(float* d, const uint32_t* a, const uint32_t* b) {
    asm volatile(
        "mma.sync.aligned.m16n8k16.row.col.f32.f16.f16.f32 "
        "{%0,%1,%2,%3}, {%4,%5,%6,%7}, {%8,%9}, {%0,%1,%2,%3};"
        : "+f"(d[0]), "+f"(d[1]), "+f"(d[2]), "+f"(d[3])
        : "r"(a[0]), "r"(a[1]), "r"(a[2]), "r"(a[3]), "r"(b[0]), "r"(b[1]));
}
__device__ __forceinline__ uint32_t pack_h2(float lo, float hi) {
    __half2 h = __floats2half2_rn(lo, hi);
    return *(uint32_t*)&h;
}

// ------------------------- device scratch ------------------------------------
__device__ float  g_offsets[BATCH * OFFCH * HW];                // 1.18 MB
__device__ __half g_wAh[(size_t)COUT * KCDIM];                  // [oc][k*256+c], fp16
__device__ float  g_sparams[(size_t)BATCH * HW * KTAPS * 8];    // 4.7 MB
__device__ float  g_stats[BATCH * GNG * 2];

// ------------------------- kernel 1: init offsets with bias ------------------
__global__ void init_offsets_kernel(const float* __restrict__ ob) {
    int i = blockIdx.x * 256 + threadIdx.x;
    if (i < BATCH * OFFCH * HW) {
        int ch = (i >> 12) % OFFCH;
        g_offsets[i] = ob[ch];
    }
}

// ------------------------- kernel 2: offset conv (3x3, 256->18) --------------
__global__ void offset_conv_kernel(const float* __restrict__ x,
                                   const float* __restrict__ ow) {
    __shared__ float ws[OFFCH * 32 * 9];
    int g    = blockIdx.x >> 6;
    int tile = blockIdx.x & 63;
    int tid  = threadIdx.x;

    for (int i = tid; i < OFFCH * 32 * 9; i += 256) {
        int j  = i % 9;
        int t  = i / 9;
        int ci = t % 32;
        int ch = t / 32;
        ws[i] = ow[(ch * CIN + g * 32 + ci) * 9 + j];
    }
    __syncthreads();

    int P  = tile * 256 + tid;
    int b  = P >> 12;
    int p  = P & 4095;
    int y  = p >> 6;
    int xx = p & 63;

    int   off[9];
    float vmask[9];
#pragma unroll
    for (int ky = 0; ky < 3; ky++)
#pragma unroll
        for (int kx = 0; kx < 3; kx++) {
            int j  = ky * 3 + kx;
            int yy = y + ky - 1, xc = xx + kx - 1;
            vmask[j] = (yy >= 0 && yy < HH && xc >= 0 && xc < WW) ? 1.0f : 0.0f;
            off[j] = (ky - 1) * WW + (kx - 1);
        }

    float acc[OFFCH];
#pragma unroll
    for (int ch = 0; ch < OFFCH; ch++) acc[ch] = 0.0f;

    const float* xb = x + ((size_t)(b * CIN + g * 32)) * HW + p;
    for (int ci = 0; ci < 32; ci++) {
        const float* xc = xb + (size_t)ci * HW;
        float v[9];
#pragma unroll
        for (int j = 0; j < 9; j++)
            v[j] = (vmask[j] != 0.0f) ? xc[off[j]] : 0.0f;
#pragma unroll
        for (int ch = 0; ch < OFFCH; ch++) {
            const float* wc = &ws[(ch * 32 + ci) * 9];
            float a = acc[ch];
#pragma unroll
            for (int j = 0; j < 9; j++) a = fmaf(wc[j], v[j], a);
            acc[ch] = a;
        }
    }
#pragma unroll
    for (int ch = 0; ch < OFFCH; ch++)
        atomicAdd(&g_offsets[(b * OFFCH + ch) * HW + p], acc[ch]);
}

// ------------------------- kernel 3: repack weights (fp16) -------------------
// deform_w[oc][c][k] -> wAh[oc][k*256+c]
__global__ void repack_w_kernel(const float* __restrict__ dw) {
    int idx = blockIdx.x * 256 + threadIdx.x;
    if (idx < COUT * KCDIM) {
        int r  = idx % KCDIM;
        int oc = idx / KCDIM;
        int k  = r >> 8;
        int c  = r & 255;
        g_wAh[idx] = __float2half_rn(dw[(size_t)oc * KCDIM + c * 9 + k]);
    }
}

// ------------------------- kernel 4: precompute bilinear params --------------
__global__ void precompute_params_kernel() {
    int P = blockIdx.x * 256 + threadIdx.x;        // 0 .. 16383
    int b = P >> 12;
    int p = P & 4095;
    int y  = p >> 6;
    int xx = p & 63;
    float* o = g_sparams + (size_t)P * (KTAPS * 8);

#pragma unroll
    for (int k = 0; k < KTAPS; k++) {
        float dy = g_offsets[(b * OFFCH + 2 * k)     * HW + p];
        float dx = g_offsets[(b * OFFCH + 2 * k + 1) * HW + p];
        int ky = k / 3, kx = k % 3;

        float py = (float)(y - 1 + ky) + dy;
        float px = (float)(xx - 1 + kx) + dx;
        float fy = floorf(py), fx = floorf(px);
        float ty = py - fy,   tx = px - fx;
        int y0 = (int)fy, x0 = (int)fx;
        int y1 = y0 + 1,  x1 = x0 + 1;

        float w00 = (1.f - ty) * (1.f - tx);
        float w01 = (1.f - ty) * tx;
        float w10 = ty * (1.f - tx);
        float w11 = ty * tx;

        bool vy0 = (y0 >= 0 && y0 < HH), vy1 = (y1 >= 0 && y1 < HH);
        bool vx0 = (x0 >= 0 && x0 < WW), vx1 = (x1 >= 0 && x1 < WW);
        if (!(vy0 && vx0)) w00 = 0.f;
        if (!(vy0 && vx1)) w01 = 0.f;
        if (!(vy1 && vx0)) w10 = 0.f;
        if (!(vy1 && vx1)) w11 = 0.f;

        int yc0 = min(max(y0, 0), HH - 1), yc1 = min(max(y1, 0), HH - 1);
        int xc0 = min(max(x0, 0), WW - 1), xc1 = min(max(x1, 0), WW - 1);

        float4 wv = make_float4(w00, w01, w10, w11);
        float4 iv = make_float4(__int_as_float(yc0 * WW + xc0),
                                __int_as_float(yc0 * WW + xc1),
                                __int_as_float(yc1 * WW + xc0),
                                __int_as_float(yc1 * WW + xc1));
        *(float4*)(o + k * 8)     = wv;
        *(float4*)(o + k * 8 + 4) = iv;
    }
}

// ------------------------- kernel 5: FUSED sample + fp16 GEMM ----------------
// One CTA: C[oc=256][p=128], 512 threads (16 warps = 4m x 4n).  Grid = 128.
// A = g_wAh (fp16, K-major) via cp.async.  B produced per chunk as fp16:
// each thread gathers 1 pixel x 8 channels x 4 corners.
// Chunk = 32 K (tap t/8, channels (t%8)*32); 2 x k16 MMA sub-chunks per chunk.
#define ASTRH 40                    // half stride per row (conflict-free: 20r+fc distinct)
#define TILE_AF_H (256 * ASTRH)     // A halfs per stage
#define TILE_BF_H (128 * ASTRH)     // B halfs per stage
#define PSTR 76                     // padded param row stride (floats)
#define PARAM_F (128 * PSTR)
#define FUSE_SMEM (PARAM_F * 4 + (2 * TILE_AF_H + 2 * TILE_BF_H) * 2)  // 100352 B
#define KT 72

__global__ void __launch_bounds__(512, 1) fused_gemm_kernel(const float* __restrict__ x,
                                                            float* __restrict__ out) {
    extern __shared__ float sm[];
    float*  sp = sm;                          // params [128 px][PSTR]
    __half* As = (__half*)(sm + PARAM_F);     // [2][256][ASTRH]
    __half* Bs = As + 2 * TILE_AF_H;          // [2][128][ASTRH]
    uint32_t As_u = smem_u32(As);

    const int tid  = threadIdx.x;
    const int lane = tid & 31;
    const int wid  = tid >> 5;
    const int wm   = wid >> 2;            // 0..3  (m offset wm*64)
    const int wn   = wid & 3;             // 0..3  (n offset wn*32)

    const int P0 = blockIdx.x * 128;
    const int b  = P0 >> 12;
    const int p0 = P0 & 4095;

    const __half* Ag = g_wAh;
    const float*  xb = x + (size_t)b * CIN * HW;

    // producer assignment: 1 pixel x 8 channels per thread
    const int ppx = tid & 127;
    const int pq  = tid >> 7;             // 0..3 : channel octet pq*8..+8

    // ---- load params into smem ----
    {
        const float4* gp = (const float4*)(g_sparams + ((size_t)b * HW + p0) * (KTAPS * 8));
#pragma unroll
        for (int n = 0; n < 5; n++) {
            int i = tid + n * 512;                 // 0..2303 float4s
            if (i < 2304) {
                float4 f = gp[i];
                int L  = i * 4;
                int px = L / 72;
                int rem = L - px * 72;
                *(float4*)&sp[px * PSTR + rem] = f;
            }
        }
    }

    // ---- A chunk 0 via cp.async (256 rows x 32 halfs; 16B = 8 halfs) ----
    const int lrow = tid >> 2;            // 0..127 (+128*it)
    const int lc8  = tid & 3;             // 8-half group
#pragma unroll
    for (int it = 0; it < 2; it++) {
        int row = lrow + it * 128;
        cp16(As_u + (row * ASTRH + lc8 * 8) * 2, Ag + (size_t)row * KCDIM + lc8 * 8);
    }
    CP_COMMIT();
    __syncthreads();                      // params visible

    // ---- produce B chunk 0 (tap 0, channels pq*8..+8) ----
    {
        float4 pa = *(float4*)&sp[ppx * PSTR];
        float4 pb = *(float4*)&sp[ppx * PSTR + 4];
        int i00 = __float_as_int(pb.x), i01 = __float_as_int(pb.y);
        int i10 = __float_as_int(pb.z), i11 = __float_as_int(pb.w);
        const float* bx = xb + (size_t)(pq * 8) * HW;
        __half* Bw = Bs + ppx * ASTRH + pq * 8;
#pragma unroll
        for (int g = 0; g < 2; g++) {
            float rv[4][4];
#pragma unroll
            for (int j = 0; j < 4; j++) {
                const float* bc = bx + (size_t)(g * 4 + j) * HW;
                rv[j][0] = bc[i00]; rv[j][1] = bc[i01];
                rv[j][2] = bc[i10]; rv[j][3] = bc[i11];
            }
            float o0 = pa.x * rv[0][0] + pa.y * rv[0][1] + pa.z * rv[0][2] + pa.w * rv[0][3];
            float o1 = pa.x * rv[1][0] + pa.y * rv[1][1] + pa.z * rv[1][2] + pa.w * rv[1][3];
            float o2 = pa.x * rv[2][0] + pa.y * rv[2][1] + pa.z * rv[2][2] + pa.w * rv[2][3];
            float o3 = pa.x * rv[3][0] + pa.y * rv[3][1] + pa.z * rv[3][2] + pa.w * rv[3][3];
            uint2 u = make_uint2(pack_h2(o0, o1), pack_h2(o2, o3));
            *(uint2*)&Bw[g * 4] = u;
        }
    }
    CP_WAIT0();
    __syncthreads();

    float acc[16][4];
#pragma unroll
    for (int i = 0; i < 16; i++)
#pragma unroll
        for (int j = 0; j < 4; j++) acc[i][j] = 0.0f;

    const int fr = lane >> 2;             // 0..7
    const int fc = lane & 3;              // 0..3

    for (int t = 0; t < KT; t++) {
        int cur = t & 1;
        int nxt = cur ^ 1;
        bool hasN = (t + 1 < KT);

        if (hasN) {
            const __half* Asrc = Ag + (t + 1) * 32;
            uint32_t aD = As_u + nxt * TILE_AF_H * 2;
#pragma unroll
            for (int it = 0; it < 2; it++) {
                int row = lrow + it * 128;
                cp16(aD + (row * ASTRH + lc8 * 8) * 2, Asrc + (size_t)row * KCDIM + lc8 * 8);
            }
            CP_COMMIT();
        }

        // params + base for B(t+1)
        float4 pa;
        int i00 = 0, i01 = 0, i10 = 0, i11 = 0;
        const float* bx = xb;
        __half* Bw = Bs + nxt * TILE_BF_H + ppx * ASTRH + pq * 8;
        if (hasN) {
            int t1  = t + 1;
            int kt1 = t1 >> 3;
            int cb1 = ((t1 & 7) << 5) + pq * 8;
            pa = *(float4*)&sp[ppx * PSTR + kt1 * 8];
            float4 pb = *(float4*)&sp[ppx * PSTR + kt1 * 8 + 4];
            i00 = __float_as_int(pb.x); i01 = __float_as_int(pb.y);
            i10 = __float_as_int(pb.z); i11 = __float_as_int(pb.w);
            bx = xb + (size_t)cb1 * HW;
        }

        const __half* Ab = As + cur * TILE_AF_H + (wm * 64) * ASTRH;
        const __half* Bb = Bs + cur * TILE_BF_H + (wn * 32) * ASTRH;

#pragma unroll
        for (int ksub = 0; ksub < 2; ksub++) {
            // issue gathers for B(t+1), group ksub (4 channels x 4 corners)
            float rv[4][4];
            if (hasN) {
#pragma unroll
                for (int j = 0; j < 4; j++) {
                    const float* bc = bx + (size_t)(ksub * 4 + j) * HW;
                    rv[j][0] = bc[i00]; rv[j][1] = bc[i01];
                    rv[j][2] = bc[i10]; rv[j][3] = bc[i11];
                }
            }

            // MMA sub-chunk ksub (k16) on current stage
            int k0 = ksub * 16;
            uint32_t af[4][4];
#pragma unroll
            for (int mt = 0; mt < 4; mt++) {
                int r0 = (mt * 16 + fr) * ASTRH;
                int r1 = (mt * 16 + fr + 8) * ASTRH;
                af[mt][0] = *(const uint32_t*)&Ab[r0 + k0 + fc * 2];
                af[mt][1] = *(const uint32_t*)&Ab[r1 + k0 + fc * 2];
                af[mt][2] = *(const uint32_t*)&Ab[r0 + k0 + fc * 2 + 8];
                af[mt][3] = *(const uint32_t*)&Ab[r1 + k0 + fc * 2 + 8];
            }
            uint32_t bf[4][2];
#pragma unroll
            for (int nt = 0; nt < 4; nt++) {
                int c0 = (nt * 8 + fr) * ASTRH;
                bf[nt][0] = *(const uint32_t*)&Bb[c0 + k0 + fc * 2];
                bf[nt][1] = *(const uint32_t*)&Bb[c0 + k0 + fc * 2 + 8];
            }
#pragma unroll
            for (int mt = 0; mt < 4; mt++)
#pragma unroll
                for (int nt = 0; nt < 4; nt++)
                    mma_f16_16x8x16(acc[mt * 4 + nt], af[mt], bf[nt]);

            // combine + store B(t+1), group ksub
            if (hasN) {
                float o0 = pa.x * rv[0][0] + pa.y * rv[0][1] + pa.z * rv[0][2] + pa.w * rv[0][3];
                float o1 = pa.x * rv[1][0] + pa.y * rv[1][1] + pa.z * rv[1][2] + pa.w * rv[1][3];
                float o2 = pa.x * rv[2][0] + pa.y * rv[2][1] + pa.z * rv[2][2] + pa.w * rv[2][3];
                float o3 = pa.x * rv[3][0] + pa.y * rv[3][1] + pa.z * rv[3][2] + pa.w * rv[3][3];
                uint2 u = make_uint2(pack_h2(o0, o1), pack_h2(o2, o3));
                *(uint2*)&Bw[ksub * 4] = u;
            }
        }

        if (hasN) CP_WAIT0();
        __syncthreads();
    }

    // epilogue
    float* ob = out + ((size_t)b * COUT + wm * 64) * HW + p0 + wn * 32;
#pragma unroll
    for (int mt = 0; mt < 4; mt++) {
#pragma unroll
        for (int nt = 0; nt < 4; nt++) {
            float* d = acc[mt * 4 + nt];
            int row0 = mt * 16 + (lane >> 2);
            int col0 = nt * 8 + 2 * (lane & 3);
            *(float2*)(ob + (size_t)row0 * HW + col0)       = make_float2(d[0], d[1]);
            *(float2*)(ob + (size_t)(row0 + 8) * HW + col0) = make_float2(d[2], d[3]);
        }
    }
}

// ------------------------- kernel 6: GroupNorm stats -------------------------
__global__ void gn_stats_kernel(const float* __restrict__ out) {
    __shared__ float sh_s[256], sh_ss[256];
    int bg = blockIdx.x;
    const float4* src = (const float4*)(out + (size_t)bg * 8 * HW);
    float s = 0.f, ss = 0.f;
    for (int i = threadIdx.x; i < 8 * HW / 4; i += 256) {
        float4 v = src[i];
        s  += v.x + v.y + v.z + v.w;
        ss += v.x * v.x + v.y * v.y + v.z * v.z + v.w * v.w;
    }
    sh_s[threadIdx.x] = s;
    sh_ss[threadIdx.x] = ss;
    __syncthreads();
    for (int stride = 128; stride > 0; stride >>= 1) {
        if (threadIdx.x < stride) {
            sh_s[threadIdx.x]  += sh_s[threadIdx.x + stride];
            sh_ss[threadIdx.x] += sh_ss[threadIdx.x + stride];
        }
        __syncthreads();
    }
    if (threadIdx.x == 0) {
        const float inv_n = 1.0f / (8.0f * HW);
        float mu  = sh_s[0] * inv_n;
        float var = sh_ss[0] * inv_n - mu * mu;
        g_stats[bg * 2]     = mu;
        g_stats[bg * 2 + 1] = rsqrtf(var + EPSGN);
    }
}

// ------------------------- kernel 7: GroupNorm apply + ReLU ------------------
__global__ void gn_apply_kernel(float* __restrict__ out,
                                const float* __restrict__ gamma,
                                const float* __restrict__ beta) {
    int i = blockIdx.x * 256 + threadIdx.x;
    if (i >= BATCH * COUT * HW / 4) return;
    int base = i * 4;
    int bg = base / (8 * HW);
    int c  = (base >> 12) & 255;
    float mu   = g_stats[bg * 2];
    float rstd = g_stats[bg * 2 + 1];
    float gsc  = gamma[c] * rstd;
    float gbi  = beta[c] - mu * gsc;
    float4* p = (float4*)out + i;
    float4 v = *p;
    v.x = fmaxf(0.f, fmaf(v.x, gsc, gbi));
    v.y = fmaxf(0.f, fmaf(v.y, gsc, gbi));
    v.z = fmaxf(0.f, fmaf(v.z, gsc, gbi));
    v.w = fmaxf(0.f, fmaf(v.w, gsc, gbi));
    *p = v;
}

// ------------------------- launch -------------------------------------------
extern "C" void kernel_launch(void* const* d_in, const int* in_sizes, int n_in,
                              void* d_out, int out_size) {
    const float* x        = (const float*)d_in[0];
    const float* offset_w = (const float*)d_in[1];
    const float* offset_b = (const float*)d_in[2];
    const float* deform_w = (const float*)d_in[3];
    const float* gn_gamma = (const float*)d_in[4];
    const float* gn_beta  = (const float*)d_in[5];
    float* out = (float*)d_out;

    static bool configured = false;
    if (!configured) {
        cudaFuncSetAttribute(fused_gemm_kernel,
                             cudaFuncAttributeMaxDynamicSharedMemorySize, FUSE_SMEM);
        configured = true;
    }

    init_offsets_kernel<<<(BATCH * OFFCH * HW + 255) / 256, 256>>>(offset_b);
    offset_conv_kernel<<<512, 256>>>(x, offset_w);
    repack_w_kernel<<<((int)(COUT * KCDIM) + 255) / 256, 256>>>(deform_w);
    precompute_params_kernel<<<BATCH * HW / 256, 256>>>();
    fused_gemm_kernel<<<BATCH * HW / 128, 512, FUSE_SMEM>>>(x, out);
    gn_stats_kernel<<<BATCH * GNG, 256>>>(out);
    gn_apply_kernel<<<(BATCH * COUT * HW / 4 + 255) / 256, 256>>>(out, gn_gamma, gn_beta);
}